// round 13
// baseline (speedup 1.0000x reference)
#include <cuda_runtime.h>
#include <cuda_fp16.h>
#include <cstdint>
#include <math.h>

// Problem constants
#define BB 4
#define TT 4096
#define DD 1024
#define HH 16
#define KP 256
#define DK 64
#define MROWS (BB*TT)          // 16384
#define BHN (BB*HH)            // 64

typedef __half half_t;

// ---------------------------------------------------------------------------
// Scratch (static device globals; no allocation allowed)
// ---------------------------------------------------------------------------
__device__ half_t g_A [(size_t)MROWS * DD];      // x plain fp16 (later ctx plain)
__device__ half_t g_Q [(size_t)MROWS * DD];      // plain
__device__ half_t g_K [(size_t)MROWS * DD];      // plain
__device__ half_t g_V [(size_t)MROWS * DD];      // plain
__device__ half_t g_Wt[4][(size_t)DD * DD];      // transposed [N][K], plain
__device__ half_t g_Eth[(size_t)2 * KP * TT];    // E^T split hi [z][kp][t]
__device__ half_t g_Etl[(size_t)2 * KP * TT];    // E^T split lo
__device__ half_t g_Kp[(size_t)BHN * KP * DK];   // plain
__device__ half_t g_Vp[(size_t)BHN * KP * DK];   // plain

// ---------------------------------------------------------------------------
// Helpers
// ---------------------------------------------------------------------------
__device__ __forceinline__ uint32_t smem_u32(const void* p) {
    uint32_t a;
    asm("{ .reg .u64 t; cvta.to.shared.u64 t, %1; cvt.u32.u64 %0, t; }" : "=r"(a) : "l"(p));
    return a;
}

#define CP_ASYNC16(dst, src) \
    asm volatile("cp.async.cg.shared.global [%0], [%1], 16;" :: "r"(dst), "l"(src))
#define CP_COMMIT() asm volatile("cp.async.commit_group;")
#define CP_WAIT1()  asm volatile("cp.async.wait_group 1;" ::: "memory")
#define CP_WAIT0()  asm volatile("cp.async.wait_group 0;" ::: "memory")

#define LDMATRIX_X4(r0, r1, r2, r3, addr) \
    asm volatile("ldmatrix.sync.aligned.m8n8.x4.shared.b16 {%0,%1,%2,%3}, [%4];" \
        : "=r"(r0), "=r"(r1), "=r"(r2), "=r"(r3) : "r"(addr))
#define LDMATRIX_X4_T(r0, r1, r2, r3, addr) \
    asm volatile("ldmatrix.sync.aligned.m8n8.x4.trans.shared.b16 {%0,%1,%2,%3}, [%4];" \
        : "=r"(r0), "=r"(r1), "=r"(r2), "=r"(r3) : "r"(addr))

// fp32-accumulate MMA
#define MMA_F16(d, a, b0_, b1_) \
    asm volatile("mma.sync.aligned.m16n8k16.row.col.f32.f16.f16.f32 " \
        "{%0,%1,%2,%3},{%4,%5,%6,%7},{%8,%9},{%0,%1,%2,%3};" \
        : "+f"((d)[0]), "+f"((d)[1]), "+f"((d)[2]), "+f"((d)[3]) \
        : "r"((a)[0]), "r"((a)[1]), "r"((a)[2]), "r"((a)[3]), "r"(b0_), "r"(b1_))

// fp16-accumulate MMA (used for tiny lo-term contributions only)
#define MMA_F16H(d, a, b0_, b1_) \
    asm volatile("mma.sync.aligned.m16n8k16.row.col.f16.f16.f16.f16 " \
        "{%0,%1},{%2,%3,%4,%5},{%6,%7},{%0,%1};" \
        : "+r"((d)[0]), "+r"((d)[1]) \
        : "r"((a)[0]), "r"((a)[1]), "r"((a)[2]), "r"((a)[3]), "r"(b0_), "r"(b1_))

__device__ __forceinline__ uint32_t pack_h2(float a, float b) {
    __half2 t = __floats2half2_rn(a, b);
    return *(uint32_t*)&t;
}

// ---------------------------------------------------------------------------
// Convert fp32 -> fp16 plain (vectorized x4)
// ---------------------------------------------------------------------------
__global__ __launch_bounds__(256) void conv_kernel(
    const float* __restrict__ src, half_t* __restrict__ dst, int n4)
{
    uint32_t* d2 = (uint32_t*)dst;
    int stride = gridDim.x * blockDim.x;
    for (int i = blockIdx.x * blockDim.x + threadIdx.x; i < n4; i += stride) {
        float4 v = ((const float4*)src)[i];
        d2[2 * i + 0] = pack_h2(v.x, v.y);
        d2[2 * i + 1] = pack_h2(v.z, v.w);
    }
}

// Transpose + convert all 4 weights (grid.z selects): [D][D] fp32 -> [N][K] fp16
__global__ __launch_bounds__(256) void wconv_kernel(
    const float* __restrict__ W0, const float* __restrict__ W1,
    const float* __restrict__ W2, const float* __restrict__ W3,
    half_t* __restrict__ WtAll)
{
    __shared__ float t[32][33];
    const int z = blockIdx.z;
    const float* W = (z == 0) ? W0 : (z == 1) ? W1 : (z == 2) ? W2 : W3;
    half_t* Wt = WtAll + (size_t)z * DD * DD;
    const int c0 = blockIdx.x * 32, r0 = blockIdx.y * 32;
    const int tx = threadIdx.x & 31, ty = threadIdx.x >> 5;
#pragma unroll
    for (int r = 0; r < 32; r += 8)
        t[ty + r][tx] = W[(size_t)(r0 + ty + r) * DD + c0 + tx];
    __syncthreads();
#pragma unroll
    for (int r = 0; r < 32; r += 8)
        Wt[(size_t)(c0 + ty + r) * DD + r0 + tx] = __float2half(t[tx][ty + r]);
}

// Transpose + split E (grid.z selects Ek/Ev): [T][KP] fp32 -> [KP][T] fp16 hi/lo
__global__ __launch_bounds__(256) void esplit_kernel(
    const float* __restrict__ E0, const float* __restrict__ E1,
    half_t* __restrict__ hiT, half_t* __restrict__ loT)
{
    __shared__ float t[32][33];
    const int z = blockIdx.z;
    const float* E = z ? E1 : E0;
    half_t* hi = hiT + (size_t)z * KP * TT;
    half_t* lo = loT + (size_t)z * KP * TT;
    const int c0 = blockIdx.x * 32, r0 = blockIdx.y * 32;
    const int tx = threadIdx.x & 31, ty = threadIdx.x >> 5;
#pragma unroll
    for (int r = 0; r < 32; r += 8)
        t[ty + r][tx] = E[(size_t)(r0 + ty + r) * KP + c0 + tx];
    __syncthreads();
#pragma unroll
    for (int r = 0; r < 32; r += 8) {
        float v = t[tx][ty + r];
        half_t h = __float2half(v);
        size_t o = (size_t)(c0 + ty + r) * TT + r0 + tx;
        hi[o] = h;
        lo[o] = __float2half(v - __half2float(h));
    }
}

// ---------------------------------------------------------------------------
// mma.sync fp16 GEMM: C = A[M,K] * B^T   (1-term A, plain everything)
// MODE 0: fp32 out (+bias).
// MODE 1: QKV routing — col block 0/1/2 -> Q/K/V plain fp16.
// Block 128x128, K-chunk 32, 8 warps, 3-stage cp.async pipeline, 2 CTAs/SM.
// ---------------------------------------------------------------------------
#define GTILE   10240                  // 128 rows * 80 B
#define GSTAGE  (2 * GTILE)            // A, B
#define TC_SMEM (3 * GSTAGE)           // 61440

template<int MODE>
__global__ __launch_bounds__(256, 2) void tc_gemm(
    const half_t* __restrict__ Ah, const half_t* __restrict__ Bh,
    float* __restrict__ C, const float* __restrict__ bias,
    half_t* __restrict__ O0, half_t* __restrict__ O1,
    half_t* __restrict__ O2, int Kn)
{
    extern __shared__ char smem[];
    const uint32_t sbase = smem_u32(smem);
    const int tid = threadIdx.x, wid = tid >> 5, lane = tid & 31;
    const int warp_m = wid >> 1, warp_n = wid & 1;
    const int m0 = blockIdx.y * 128;
    const int n0g = blockIdx.x * 128;

    float acc[2][8][4];
#pragma unroll
    for (int mt = 0; mt < 2; mt++)
#pragma unroll
        for (int nt = 0; nt < 8; nt++)
#pragma unroll
            for (int q = 0; q < 4; q++) acc[mt][nt][q] = 0.f;

    const uint32_t lofs = ((((lane >> 3) & 1) * 8 + (lane & 7)) * 80u) + ((lane >> 4) * 16u);
    const int ld_row0 = tid >> 2;
    const int ld_col  = tid & 3;

    const int NC = Kn >> 5;
#define LOAD_STAGE(s, k0v) do {                                                   \
        const uint32_t stg = sbase + (uint32_t)(s) * GSTAGE;                      \
        _Pragma("unroll")                                                         \
        for (int i = 0; i < 4; i++) {                                             \
            const int t = i >> 1;                                                 \
            const int row = (i & 1) * 64 + ld_row0;                               \
            const half_t* sp = (t == 0 ? Ah : Bh);                                \
            const int grow = (t == 0 ? m0 : n0g) + row;                           \
            CP_ASYNC16(stg + t * GTILE + row * 80 + ld_col * 16,                  \
                       sp + (size_t)grow * Kn + (k0v) + ld_col * 8);              \
        }                                                                         \
        CP_COMMIT();                                                              \
    } while (0)

    LOAD_STAGE(0, 0);
    LOAD_STAGE(1, 32);

    for (int c = 0; c < NC; c++) {
        const bool more = (c + 2 < NC);
        if (more) { CP_WAIT1(); } else { CP_WAIT0(); }   // tail: full drain
        __syncthreads();
        if (more) LOAD_STAGE((c + 2) % 3, (c + 2) << 5);

        const uint32_t stg = sbase + (uint32_t)(c % 3) * GSTAGE;
        const uint32_t a_base = stg + (warp_m * 32) * 80 + lofs;
        const uint32_t b_base = stg + GTILE + (warp_n * 64) * 80 + lofs;

#pragma unroll
        for (int ks = 0; ks < 2; ks++) {
            uint32_t ah[2][4], b[4][4];
#pragma unroll
            for (int mt = 0; mt < 2; mt++)
                LDMATRIX_X4(ah[mt][0], ah[mt][1], ah[mt][2], ah[mt][3],
                            a_base + mt * (16 * 80) + ks * 32);
#pragma unroll
            for (int nq = 0; nq < 4; nq++)
                LDMATRIX_X4(b[nq][0], b[nq][1], b[nq][2], b[nq][3],
                            b_base + nq * (16 * 80) + ks * 32);
#pragma unroll
            for (int mt = 0; mt < 2; mt++)
#pragma unroll
                for (int nt = 0; nt < 8; nt++) {
                    const int nq = nt >> 1, sel = nt & 1;
                    MMA_F16(acc[mt][nt], ah[mt], b[nq][sel], b[nq][sel + 2]);
                }
        }
    }
#undef LOAD_STAGE

    const int g = lane >> 2, tig = lane & 3;
#pragma unroll
    for (int mt = 0; mt < 2; mt++) {
        const int row0 = m0 + warp_m * 32 + mt * 16 + g;
#pragma unroll
        for (int nt = 0; nt < 8; nt++) {
            const int colg = n0g + warp_n * 64 + nt * 8 + 2 * tig;
            if (MODE == 0) {
                float bx = 0.f, by = 0.f;
                if (bias) { bx = bias[colg]; by = bias[colg + 1]; }
                *(float2*)(C + (size_t)row0 * DD + colg) =
                    make_float2(acc[mt][nt][0] + bx, acc[mt][nt][1] + by);
                *(float2*)(C + (size_t)(row0 + 8) * DD + colg) =
                    make_float2(acc[mt][nt][2] + bx, acc[mt][nt][3] + by);
            } else {
                const int which = colg >> 10;
                const int col = colg & 1023;
                half_t* O = (which == 0) ? O0 : (which == 1) ? O1 : O2;
                const size_t o0 = (size_t)row0 * DD + col;
                const size_t o1 = (size_t)(row0 + 8) * DD + col;
                *(uint32_t*)(O + o0) = pack_h2(acc[mt][nt][0], acc[mt][nt][1]);
                *(uint32_t*)(O + o1) = pack_h2(acc[mt][nt][2], acc[mt][nt][3]);
            }
        }
    }
}

// ---------------------------------------------------------------------------
// Low-rank projection on MMA, 3-stage pipeline, uniform 2-term:
//   Cp[kp][d] = (Eh+El)^T[kp][t] * X[t][h*64+d], plain output
//   E-hi term -> fp32 accumulators; E-lo term -> fp16 accumulators (tiny
//   magnitude, fp16 accumulation error negligible), merged in epilogue.
// grid = (KP/128, BHN, 2)
// ---------------------------------------------------------------------------
#define PAH 0
#define PALo 10240
#define PB  20480
#define PSTAGE (PB + 32 * 144)          // 25088
#define PROJ_SMEM (3 * PSTAGE)          // 75264

__global__ __launch_bounds__(256) void proj_mma(
    const half_t* __restrict__ Eh, const half_t* __restrict__ El,
    const half_t* __restrict__ Kb, const half_t* __restrict__ Vb,
    half_t* __restrict__ Kp, half_t* __restrict__ Vp)
{
    extern __shared__ char smem[];
    const uint32_t sbase = smem_u32(smem);
    const int tid = threadIdx.x, wid = tid >> 5, lane = tid & 31;
    const int m0k = blockIdx.x * 128;
    const int bh = blockIdx.y, z = blockIdx.z;
    const int b = bh >> 4, h = bh & 15;

    const half_t* X = z ? Vb : Kb;
    half_t* O = z ? Vp : Kp;
    const size_t eoff = (size_t)z * KP * TT;
    const size_t brow = (size_t)b * TT;
    const int hcol = h * 64;

    float cacc[8][4];
    uint32_t lacc[8][2];
#pragma unroll
    for (int nt = 0; nt < 8; nt++) {
#pragma unroll
        for (int q = 0; q < 4; q++) cacc[nt][q] = 0.f;
        lacc[nt][0] = 0u; lacc[nt][1] = 0u;
    }

    const uint32_t lofsA = (lane & 15) * 80u + ((lane >> 4) * 16u);
    const uint32_t lofsB = (lane & 15) * 144u + ((lane >> 4) * 16u);
    const int wm = wid * 16;

#define PROJ_LOAD(s, k0v) do {                                                    \
        const uint32_t stg = sbase + (uint32_t)(s) * PSTAGE;                      \
        _Pragma("unroll")                                                         \
        for (int i = 0; i < 2; i++) {                                             \
            const int idx = tid + i * 256;                                        \
            const int r = idx >> 2, cc = idx & 3;                                 \
            const size_t gof = (size_t)(m0k + r) * TT + (k0v) + cc * 8;           \
            CP_ASYNC16(stg + PAH + r * 80 + cc * 16, Eh + eoff + gof);            \
            CP_ASYNC16(stg + PALo + r * 80 + cc * 16, El + eoff + gof);           \
        }                                                                         \
        {                                                                         \
            const int r = tid >> 3, cc = tid & 7;                                 \
            const size_t gof = (brow + (k0v) + r) * DD + hcol + cc * 8;           \
            CP_ASYNC16(stg + PB + r * 144 + cc * 16, X + gof);                    \
        }                                                                         \
        CP_COMMIT();                                                              \
    } while (0)

    PROJ_LOAD(0, 0);
    PROJ_LOAD(1, 32);
    const int NC = TT >> 5;
    for (int c = 0; c < NC; c++) {
        const bool more = (c + 2 < NC);
        if (more) { CP_WAIT1(); } else { CP_WAIT0(); }   // tail: full drain
        __syncthreads();
        if (more) PROJ_LOAD((c + 2) % 3, (c + 2) << 5);

        const uint32_t stg = sbase + (uint32_t)(c % 3) * PSTAGE;
#pragma unroll
        for (int s = 0; s < 2; s++) {
            uint32_t ah[4], al[4], bb[4][4];
            LDMATRIX_X4(ah[0], ah[1], ah[2], ah[3], stg + PAH + wm * 80 + lofsA + s * 32);
            LDMATRIX_X4(al[0], al[1], al[2], al[3], stg + PALo + wm * 80 + lofsA + s * 32);
#pragma unroll
            for (int ng = 0; ng < 4; ng++)
                LDMATRIX_X4_T(bb[ng][0], bb[ng][1], bb[ng][2], bb[ng][3],
                              stg + PB + s * (16 * 144) + lofsB + ng * 32);
            // hi-term MMAs (fp32 accum)
#pragma unroll
            for (int ng = 0; ng < 4; ng++) {
                MMA_F16(cacc[2 * ng], ah, bb[ng][0], bb[ng][1]);
                MMA_F16(cacc[2 * ng + 1], ah, bb[ng][2], bb[ng][3]);
            }
            // lo-term MMAs (fp16 accum — tiny magnitudes)
#pragma unroll
            for (int ng = 0; ng < 4; ng++) {
                MMA_F16H(lacc[2 * ng], al, bb[ng][0], bb[ng][1]);
                MMA_F16H(lacc[2 * ng + 1], al, bb[ng][2], bb[ng][3]);
            }
        }
    }
#undef PROJ_LOAD

    const int g = lane >> 2, tig = lane & 3;
    const size_t obase = (size_t)bh * KP * DK;
#pragma unroll
    for (int nt = 0; nt < 8; nt++) {
        // merge fp16 lo accumulators
        __half2 p0 = *(__half2*)&lacc[nt][0];
        __half2 p1 = *(__half2*)&lacc[nt][1];
        float v0 = cacc[nt][0] + __low2float(p0);
        float v1 = cacc[nt][1] + __high2float(p0);
        float v2 = cacc[nt][2] + __low2float(p1);
        float v3 = cacc[nt][3] + __high2float(p1);
        const int row0 = m0k + wm + g;
        const int col = nt * 8 + 2 * tig;
        *(uint32_t*)(O + obase + (size_t)row0 * DK + col) = pack_h2(v0, v1);
        *(uint32_t*)(O + obase + (size_t)(row0 + 8) * DK + col) = pack_h2(v2, v3);
    }
}

// ---------------------------------------------------------------------------
// Fused MMA attention per (bh, 128-row t-tile):
//   S = Q*Kp^T (1-term, fp32 accum)
//   softmax on fragments; ctx = P*Vp (1-term); ctx plain fp16 to Ch.
// ---------------------------------------------------------------------------
#define AQ 0
#define AK (AQ + 128 * 144)
#define AV (AK + 256 * 144)
#define ATTN_SMEM (AV + 256 * 144)      // 92160

__global__ __launch_bounds__(256) void attn_mma(
    const half_t* __restrict__ Q, const half_t* __restrict__ Kp,
    const half_t* __restrict__ Vp, half_t* __restrict__ Ch)
{
    extern __shared__ char smem[];
    const uint32_t sbase = smem_u32(smem);
    const int tid = threadIdx.x, wid = tid >> 5, lane = tid & 31;
    const int bh = blockIdx.y, b = bh >> 4, h = bh & 15;
    const int t0 = blockIdx.x * 128;

    const size_t qbase = (size_t)(b * TT + t0) * DD + h * 64;
    for (int idx = tid; idx < 128 * 8; idx += 256) {
        const int r = idx >> 3, c = idx & 7;
        *(uint4*)(smem + AQ + r * 144 + c * 16) =
            *(const uint4*)(Q + qbase + (size_t)r * DD + c * 8);
    }
    const size_t kpb = (size_t)bh * KP * DK;
    for (int idx = tid; idx < 256 * 8; idx += 256) {
        const int r = idx >> 3, c = idx & 7;
        const size_t go = kpb + (size_t)r * DK + c * 8;
        *(uint4*)(smem + AK + r * 144 + c * 16) = *(const uint4*)(Kp + go);
        *(uint4*)(smem + AV + r * 144 + c * 16) = *(const uint4*)(Vp + go);
    }
    __syncthreads();

    const int wm = wid * 16;
    const uint32_t lofs = (lane & 15) * 144u + ((lane >> 4) * 16u);

    // --- scores (1-term), ng in batches of 4 ---
    float sacc[32][4];
#pragma unroll
    for (int j = 0; j < 32; j++)
#pragma unroll
        for (int q = 0; q < 4; q++) sacc[j][q] = 0.f;

#pragma unroll
    for (int s = 0; s < 4; s++) {
        uint32_t q4[4], bb[4][4];
        LDMATRIX_X4(q4[0], q4[1], q4[2], q4[3], sbase + AQ + wm * 144 + lofs + s * 32);
#pragma unroll
        for (int g4 = 0; g4 < 4; g4++) {
#pragma unroll
            for (int j = 0; j < 4; j++)
                LDMATRIX_X4(bb[j][0], bb[j][1], bb[j][2], bb[j][3],
                            sbase + AK + (g4 * 4 + j) * (16 * 144) + lofs + s * 32);
#pragma unroll
            for (int j = 0; j < 4; j++) {
                const int ng = g4 * 4 + j;
                MMA_F16(sacc[2 * ng], q4, bb[j][0], bb[j][2]);
                MMA_F16(sacc[2 * ng + 1], q4, bb[j][1], bb[j][3]);
            }
        }
    }

    // --- softmax on fragments ---
    float m0 = -1e30f, m1 = -1e30f;
#pragma unroll
    for (int j = 0; j < 32; j++) {
        m0 = fmaxf(m0, fmaxf(sacc[j][0], sacc[j][1]));
        m1 = fmaxf(m1, fmaxf(sacc[j][2], sacc[j][3]));
    }
    m0 = fmaxf(m0, __shfl_xor_sync(0xffffffffu, m0, 1));
    m0 = fmaxf(m0, __shfl_xor_sync(0xffffffffu, m0, 2));
    m1 = fmaxf(m1, __shfl_xor_sync(0xffffffffu, m1, 1));
    m1 = fmaxf(m1, __shfl_xor_sync(0xffffffffu, m1, 2));

    float sum0 = 0.f, sum1 = 0.f;
#pragma unroll
    for (int j = 0; j < 32; j++) {
        float e0 = __expf((sacc[j][0] - m0) * 0.125f);
        float e1 = __expf((sacc[j][1] - m0) * 0.125f);
        float e2 = __expf((sacc[j][2] - m1) * 0.125f);
        float e3 = __expf((sacc[j][3] - m1) * 0.125f);
        sacc[j][0] = e0; sacc[j][1] = e1; sacc[j][2] = e2; sacc[j][3] = e3;
        sum0 += e0 + e1; sum1 += e2 + e3;
    }
    sum0 += __shfl_xor_sync(0xffffffffu, sum0, 1);
    sum0 += __shfl_xor_sync(0xffffffffu, sum0, 2);
    sum1 += __shfl_xor_sync(0xffffffffu, sum1, 1);
    sum1 += __shfl_xor_sync(0xffffffffu, sum1, 2);
    const float inv0 = __frcp_rn(sum0), inv1 = __frcp_rn(sum1);

    // --- ctx = P * Vp (1-term, P plain fp16) ---
    float cacc[8][4];
#pragma unroll
    for (int nt = 0; nt < 8; nt++)
#pragma unroll
        for (int q = 0; q < 4; q++) cacc[nt][q] = 0.f;

#pragma unroll
    for (int s = 0; s < 16; s++) {
        uint32_t ap[4], bb[4][4];
        ap[0] = pack_h2(sacc[2 * s][0],     sacc[2 * s][1]);
        ap[1] = pack_h2(sacc[2 * s][2],     sacc[2 * s][3]);
        ap[2] = pack_h2(sacc[2 * s + 1][0], sacc[2 * s + 1][1]);
        ap[3] = pack_h2(sacc[2 * s + 1][2], sacc[2 * s + 1][3]);
#pragma unroll
        for (int ng = 0; ng < 4; ng++)
            LDMATRIX_X4_T(bb[ng][0], bb[ng][1], bb[ng][2], bb[ng][3],
                          sbase + AV + s * (16 * 144) + lofs + ng * 32);
#pragma unroll
        for (int ng = 0; ng < 4; ng++) {
            MMA_F16(cacc[2 * ng], ap, bb[ng][0], bb[ng][1]);
            MMA_F16(cacc[2 * ng + 1], ap, bb[ng][2], bb[ng][3]);
        }
    }

    // --- epilogue: normalize, write plain fp16 ctx ---
    const int g = lane >> 2, tig = lane & 3;
    const size_t r0 = (size_t)(b * TT + t0 + wm + g) * DD + h * 64;
    const size_t r1 = r0 + 8 * DD;
#pragma unroll
    for (int nt = 0; nt < 8; nt++) {
        const int col = nt * 8 + 2 * tig;
        *(uint32_t*)(Ch + r0 + col) = pack_h2(cacc[nt][0] * inv0, cacc[nt][1] * inv0);
        *(uint32_t*)(Ch + r1 + col) = pack_h2(cacc[nt][2] * inv1, cacc[nt][3] * inv1);
    }
}

// ---------------------------------------------------------------------------
// Launch
// ---------------------------------------------------------------------------
extern "C" void kernel_launch(void* const* d_in, const int* in_sizes, int n_in,
                              void* d_out, int out_size)
{
    const float* x  = (const float*)d_in[0];
    const float* Wq = (const float*)d_in[1];
    const float* Wk = (const float*)d_in[2];
    const float* Wv = (const float*)d_in[3];
    const float* Ek = (const float*)d_in[4];
    const float* Ev = (const float*)d_in[5];
    const float* Wo = (const float*)d_in[6];
    const float* bo = (const float*)d_in[7];
    float* out = (float*)d_out;

    half_t *Ap, *Qp, *Kbp, *Vbp, *Wtp, *Ethp, *Etlp, *Kpp, *Vpp;
    cudaGetSymbolAddress((void**)&Ap,  g_A);
    cudaGetSymbolAddress((void**)&Qp,  g_Q);
    cudaGetSymbolAddress((void**)&Kbp, g_K);
    cudaGetSymbolAddress((void**)&Vbp, g_V);
    cudaGetSymbolAddress((void**)&Wtp, g_Wt);
    cudaGetSymbolAddress((void**)&Ethp, g_Eth);
    cudaGetSymbolAddress((void**)&Etlp, g_Etl);
    cudaGetSymbolAddress((void**)&Kpp, g_Kp);
    cudaGetSymbolAddress((void**)&Vpp, g_Vp);

    const size_t WSZ = (size_t)DD * DD;

    cudaFuncSetAttribute(tc_gemm<1>, cudaFuncAttributeMaxDynamicSharedMemorySize, TC_SMEM);
    cudaFuncSetAttribute(tc_gemm<0>, cudaFuncAttributeMaxDynamicSharedMemorySize, TC_SMEM);
    cudaFuncSetAttribute(proj_mma, cudaFuncAttributeMaxDynamicSharedMemorySize, PROJ_SMEM);
    cudaFuncSetAttribute(attn_mma, cudaFuncAttributeMaxDynamicSharedMemorySize, ATTN_SMEM);

    // 1) convert x -> fp16 plain
    conv_kernel<<<2048, 256>>>(x, Ap, MROWS * DD / 4);
    // 2) transpose+convert weights (plain) + split E
    wconv_kernel<<<dim3(DD / 32, DD / 32, 4), 256>>>(Wq, Wk, Wv, Wo, Wtp);
    esplit_kernel<<<dim3(KP / 32, TT / 32, 2), 256>>>(Ek, Ev, Ethp, Etlp);

    // 3) fused QKV projection (1-term, all-plain outputs)
    tc_gemm<1><<<dim3(3 * DD / 128, MROWS / 128), 256, TC_SMEM>>>(
        Ap, Wtp, nullptr, nullptr, Qp, Kbp, Vbp, DD);

    // 4) low-rank projections (2-term; lo term in fp16 accum)
    proj_mma<<<dim3(KP / 128, BHN, 2), 256, PROJ_SMEM>>>(
        Ethp, Etlp, Kbp, Vbp, Kpp, Vpp);

    // 5) fused attention -> ctx plain fp16 into A buffer
    attn_mma<<<dim3(TT / 128, BHN), 256, ATTN_SMEM>>>(
        Qp, Kpp, Vpp, Ap);

    // 6) output projection + bias (1-term, fp32 out)
    tc_gemm<0><<<dim3(DD / 128, MROWS / 128), 256, TC_SMEM>>>(
        Ap, Wtp + 3 * WSZ, out, bo, nullptr, nullptr, nullptr, DD);
}

// round 14
// speedup vs baseline: 1.4932x; 1.4932x over previous
#include <cuda_runtime.h>
#include <cuda_fp16.h>
#include <cstdint>
#include <math.h>

// Problem constants
#define BB 4
#define TT 4096
#define DD 1024
#define HH 16
#define KP 256
#define DK 64
#define MROWS (BB*TT)          // 16384
#define BHN (BB*HH)            // 64

typedef __half half_t;

// ---------------------------------------------------------------------------
// Scratch (static device globals; no allocation allowed)
// ---------------------------------------------------------------------------
__device__ half_t g_A [(size_t)MROWS * DD];      // x plain fp16 (later ctx plain)
__device__ half_t g_Q [(size_t)MROWS * DD];      // plain
__device__ half_t g_K [(size_t)MROWS * DD];      // plain
__device__ half_t g_V [(size_t)MROWS * DD];      // plain
__device__ half_t g_Wt[4][(size_t)DD * DD];      // transposed [N][K], plain
__device__ half_t g_Eth[(size_t)2 * KP * TT];    // E^T split hi [z][kp][t]
__device__ half_t g_Etl[(size_t)2 * KP * TT];    // E^T split lo
__device__ half_t g_Kp[(size_t)BHN * KP * DK];   // plain
__device__ half_t g_Vp[(size_t)BHN * KP * DK];   // plain

// ---------------------------------------------------------------------------
// Helpers
// ---------------------------------------------------------------------------
__device__ __forceinline__ uint32_t smem_u32(const void* p) {
    uint32_t a;
    asm("{ .reg .u64 t; cvta.to.shared.u64 t, %1; cvt.u32.u64 %0, t; }" : "=r"(a) : "l"(p));
    return a;
}

#define CP_ASYNC16(dst, src) \
    asm volatile("cp.async.cg.shared.global [%0], [%1], 16;" :: "r"(dst), "l"(src))
#define CP_COMMIT() asm volatile("cp.async.commit_group;")
#define CP_WAIT1()  asm volatile("cp.async.wait_group 1;" ::: "memory")
#define CP_WAIT0()  asm volatile("cp.async.wait_group 0;" ::: "memory")

#define LDMATRIX_X4(r0, r1, r2, r3, addr) \
    asm volatile("ldmatrix.sync.aligned.m8n8.x4.shared.b16 {%0,%1,%2,%3}, [%4];" \
        : "=r"(r0), "=r"(r1), "=r"(r2), "=r"(r3) : "r"(addr))
#define LDMATRIX_X4_T(r0, r1, r2, r3, addr) \
    asm volatile("ldmatrix.sync.aligned.m8n8.x4.trans.shared.b16 {%0,%1,%2,%3}, [%4];" \
        : "=r"(r0), "=r"(r1), "=r"(r2), "=r"(r3) : "r"(addr))

#define MMA_F16(d, a, b0_, b1_) \
    asm volatile("mma.sync.aligned.m16n8k16.row.col.f32.f16.f16.f32 " \
        "{%0,%1,%2,%3},{%4,%5,%6,%7},{%8,%9},{%0,%1,%2,%3};" \
        : "+f"((d)[0]), "+f"((d)[1]), "+f"((d)[2]), "+f"((d)[3]) \
        : "r"((a)[0]), "r"((a)[1]), "r"((a)[2]), "r"((a)[3]), "r"(b0_), "r"(b1_))

__device__ __forceinline__ uint32_t pack_h2(float a, float b) {
    __half2 t = __floats2half2_rn(a, b);
    return *(uint32_t*)&t;
}

// ---------------------------------------------------------------------------
// Convert fp32 -> fp16 plain (vectorized x4)
// ---------------------------------------------------------------------------
__global__ __launch_bounds__(256) void conv_kernel(
    const float* __restrict__ src, half_t* __restrict__ dst, int n4)
{
    uint32_t* d2 = (uint32_t*)dst;
    int stride = gridDim.x * blockDim.x;
    for (int i = blockIdx.x * blockDim.x + threadIdx.x; i < n4; i += stride) {
        float4 v = ((const float4*)src)[i];
        d2[2 * i + 0] = pack_h2(v.x, v.y);
        d2[2 * i + 1] = pack_h2(v.z, v.w);
    }
}

// Transpose + convert all 4 weights (grid.z selects): [D][D] fp32 -> [N][K] fp16
__global__ __launch_bounds__(256) void wconv_kernel(
    const float* __restrict__ W0, const float* __restrict__ W1,
    const float* __restrict__ W2, const float* __restrict__ W3,
    half_t* __restrict__ WtAll)
{
    __shared__ float t[32][33];
    const int z = blockIdx.z;
    const float* W = (z == 0) ? W0 : (z == 1) ? W1 : (z == 2) ? W2 : W3;
    half_t* Wt = WtAll + (size_t)z * DD * DD;
    const int c0 = blockIdx.x * 32, r0 = blockIdx.y * 32;
    const int tx = threadIdx.x & 31, ty = threadIdx.x >> 5;
#pragma unroll
    for (int r = 0; r < 32; r += 8)
        t[ty + r][tx] = W[(size_t)(r0 + ty + r) * DD + c0 + tx];
    __syncthreads();
#pragma unroll
    for (int r = 0; r < 32; r += 8)
        Wt[(size_t)(c0 + ty + r) * DD + r0 + tx] = __float2half(t[tx][ty + r]);
}

// Transpose + split E (grid.z selects Ek/Ev): [T][KP] fp32 -> [KP][T] fp16 hi/lo
__global__ __launch_bounds__(256) void esplit_kernel(
    const float* __restrict__ E0, const float* __restrict__ E1,
    half_t* __restrict__ hiT, half_t* __restrict__ loT)
{
    __shared__ float t[32][33];
    const int z = blockIdx.z;
    const float* E = z ? E1 : E0;
    half_t* hi = hiT + (size_t)z * KP * TT;
    half_t* lo = loT + (size_t)z * KP * TT;
    const int c0 = blockIdx.x * 32, r0 = blockIdx.y * 32;
    const int tx = threadIdx.x & 31, ty = threadIdx.x >> 5;
#pragma unroll
    for (int r = 0; r < 32; r += 8)
        t[ty + r][tx] = E[(size_t)(r0 + ty + r) * KP + c0 + tx];
    __syncthreads();
#pragma unroll
    for (int r = 0; r < 32; r += 8) {
        float v = t[tx][ty + r];
        half_t h = __float2half(v);
        size_t o = (size_t)(c0 + ty + r) * TT + r0 + tx;
        hi[o] = h;
        lo[o] = __float2half(v - __half2float(h));
    }
}

// ---------------------------------------------------------------------------
// mma.sync fp16 GEMM: C = A[M,K] * B^T   (1-term A, plain everything)
// MODE 0: fp32 out (+bias).
// MODE 1: QKV routing — col block 0/1/2 -> Q/K/V plain fp16.
// Block 128x128, K-chunk 32, 8 warps, 3-stage cp.async pipeline, 2 CTAs/SM.
// ---------------------------------------------------------------------------
#define GTILE   10240                  // 128 rows * 80 B
#define GSTAGE  (2 * GTILE)            // A, B
#define TC_SMEM (3 * GSTAGE)           // 61440

template<int MODE>
__global__ __launch_bounds__(256, 2) void tc_gemm(
    const half_t* __restrict__ Ah, const half_t* __restrict__ Bh,
    float* __restrict__ C, const float* __restrict__ bias,
    half_t* __restrict__ O0, half_t* __restrict__ O1,
    half_t* __restrict__ O2, int Kn)
{
    extern __shared__ char smem[];
    const uint32_t sbase = smem_u32(smem);
    const int tid = threadIdx.x, wid = tid >> 5, lane = tid & 31;
    const int warp_m = wid >> 1, warp_n = wid & 1;
    const int m0 = blockIdx.y * 128;
    const int n0g = blockIdx.x * 128;

    float acc[2][8][4];
#pragma unroll
    for (int mt = 0; mt < 2; mt++)
#pragma unroll
        for (int nt = 0; nt < 8; nt++)
#pragma unroll
            for (int q = 0; q < 4; q++) acc[mt][nt][q] = 0.f;

    const uint32_t lofs = ((((lane >> 3) & 1) * 8 + (lane & 7)) * 80u) + ((lane >> 4) * 16u);
    const int ld_row0 = tid >> 2;
    const int ld_col  = tid & 3;

    const int NC = Kn >> 5;
#define LOAD_STAGE(s, k0v) do {                                                   \
        const uint32_t stg = sbase + (uint32_t)(s) * GSTAGE;                      \
        _Pragma("unroll")                                                         \
        for (int i = 0; i < 4; i++) {                                             \
            const int t = i >> 1;                                                 \
            const int row = (i & 1) * 64 + ld_row0;                               \
            const half_t* sp = (t == 0 ? Ah : Bh);                                \
            const int grow = (t == 0 ? m0 : n0g) + row;                           \
            CP_ASYNC16(stg + t * GTILE + row * 80 + ld_col * 16,                  \
                       sp + (size_t)grow * Kn + (k0v) + ld_col * 8);              \
        }                                                                         \
        CP_COMMIT();                                                              \
    } while (0)

    LOAD_STAGE(0, 0);
    LOAD_STAGE(1, 32);

    for (int c = 0; c < NC; c++) {
        const bool more = (c + 2 < NC);
        if (more) { CP_WAIT1(); } else { CP_WAIT0(); }   // tail: full drain
        __syncthreads();
        if (more) LOAD_STAGE((c + 2) % 3, (c + 2) << 5);

        const uint32_t stg = sbase + (uint32_t)(c % 3) * GSTAGE;
        const uint32_t a_base = stg + (warp_m * 32) * 80 + lofs;
        const uint32_t b_base = stg + GTILE + (warp_n * 64) * 80 + lofs;

#pragma unroll
        for (int ks = 0; ks < 2; ks++) {
            uint32_t ah[2][4], b[4][4];
#pragma unroll
            for (int mt = 0; mt < 2; mt++)
                LDMATRIX_X4(ah[mt][0], ah[mt][1], ah[mt][2], ah[mt][3],
                            a_base + mt * (16 * 80) + ks * 32);
#pragma unroll
            for (int nq = 0; nq < 4; nq++)
                LDMATRIX_X4(b[nq][0], b[nq][1], b[nq][2], b[nq][3],
                            b_base + nq * (16 * 80) + ks * 32);
#pragma unroll
            for (int mt = 0; mt < 2; mt++)
#pragma unroll
                for (int nt = 0; nt < 8; nt++) {
                    const int nq = nt >> 1, sel = nt & 1;
                    MMA_F16(acc[mt][nt], ah[mt], b[nq][sel], b[nq][sel + 2]);
                }
        }
    }
#undef LOAD_STAGE

    const int g = lane >> 2, tig = lane & 3;
#pragma unroll
    for (int mt = 0; mt < 2; mt++) {
        const int row0 = m0 + warp_m * 32 + mt * 16 + g;
#pragma unroll
        for (int nt = 0; nt < 8; nt++) {
            const int colg = n0g + warp_n * 64 + nt * 8 + 2 * tig;
            if (MODE == 0) {
                float bx = 0.f, by = 0.f;
                if (bias) { bx = bias[colg]; by = bias[colg + 1]; }
                *(float2*)(C + (size_t)row0 * DD + colg) =
                    make_float2(acc[mt][nt][0] + bx, acc[mt][nt][1] + by);
                *(float2*)(C + (size_t)(row0 + 8) * DD + colg) =
                    make_float2(acc[mt][nt][2] + bx, acc[mt][nt][3] + by);
            } else {
                const int which = colg >> 10;
                const int col = colg & 1023;
                half_t* O = (which == 0) ? O0 : (which == 1) ? O1 : O2;
                const size_t o0 = (size_t)row0 * DD + col;
                const size_t o1 = (size_t)(row0 + 8) * DD + col;
                *(uint32_t*)(O + o0) = pack_h2(acc[mt][nt][0], acc[mt][nt][1]);
                *(uint32_t*)(O + o1) = pack_h2(acc[mt][nt][2], acc[mt][nt][3]);
            }
        }
    }
}

// ---------------------------------------------------------------------------
// Low-rank projection on MMA, 3-stage pipeline, uniform 2-term (fp32 accum):
//   Cp[kp][d] = (Eh+El)^T[kp][t] * X[t][h*64+d], plain output
// grid = (KP/128, BHN, 2)
// ---------------------------------------------------------------------------
#define PAH 0
#define PALo 10240
#define PB  20480
#define PSTAGE (PB + 32 * 144)          // 25088
#define PROJ_SMEM (3 * PSTAGE)          // 75264

__global__ __launch_bounds__(256) void proj_mma(
    const half_t* __restrict__ Eh, const half_t* __restrict__ El,
    const half_t* __restrict__ Kb, const half_t* __restrict__ Vb,
    half_t* __restrict__ Kp, half_t* __restrict__ Vp)
{
    extern __shared__ char smem[];
    const uint32_t sbase = smem_u32(smem);
    const int tid = threadIdx.x, wid = tid >> 5, lane = tid & 31;
    const int m0k = blockIdx.x * 128;
    const int bh = blockIdx.y, z = blockIdx.z;
    const int b = bh >> 4, h = bh & 15;

    const half_t* X = z ? Vb : Kb;
    half_t* O = z ? Vp : Kp;
    const size_t eoff = (size_t)z * KP * TT;
    const size_t brow = (size_t)b * TT;
    const int hcol = h * 64;

    float cacc[8][4];
#pragma unroll
    for (int nt = 0; nt < 8; nt++)
#pragma unroll
        for (int q = 0; q < 4; q++) cacc[nt][q] = 0.f;

    const uint32_t lofsA = (lane & 15) * 80u + ((lane >> 4) * 16u);
    const uint32_t lofsB = (lane & 15) * 144u + ((lane >> 4) * 16u);
    const int wm = wid * 16;

#define PROJ_LOAD(s, k0v) do {                                                    \
        const uint32_t stg = sbase + (uint32_t)(s) * PSTAGE;                      \
        _Pragma("unroll")                                                         \
        for (int i = 0; i < 2; i++) {                                             \
            const int idx = tid + i * 256;                                        \
            const int r = idx >> 2, cc = idx & 3;                                 \
            const size_t gof = (size_t)(m0k + r) * TT + (k0v) + cc * 8;           \
            CP_ASYNC16(stg + PAH + r * 80 + cc * 16, Eh + eoff + gof);            \
            CP_ASYNC16(stg + PALo + r * 80 + cc * 16, El + eoff + gof);           \
        }                                                                         \
        {                                                                         \
            const int r = tid >> 3, cc = tid & 7;                                 \
            const size_t gof = (brow + (k0v) + r) * DD + hcol + cc * 8;           \
            CP_ASYNC16(stg + PB + r * 144 + cc * 16, X + gof);                    \
        }                                                                         \
        CP_COMMIT();                                                              \
    } while (0)

    PROJ_LOAD(0, 0);
    PROJ_LOAD(1, 32);
    const int NC = TT >> 5;
    for (int c = 0; c < NC; c++) {
        const bool more = (c + 2 < NC);
        if (more) { CP_WAIT1(); } else { CP_WAIT0(); }   // tail: full drain
        __syncthreads();
        if (more) PROJ_LOAD((c + 2) % 3, (c + 2) << 5);

        const uint32_t stg = sbase + (uint32_t)(c % 3) * PSTAGE;
#pragma unroll
        for (int s = 0; s < 2; s++) {
            uint32_t ah[4], al[4], bb[4][4];
            LDMATRIX_X4(ah[0], ah[1], ah[2], ah[3], stg + PAH + wm * 80 + lofsA + s * 32);
            LDMATRIX_X4(al[0], al[1], al[2], al[3], stg + PALo + wm * 80 + lofsA + s * 32);
#pragma unroll
            for (int ng = 0; ng < 4; ng++)
                LDMATRIX_X4_T(bb[ng][0], bb[ng][1], bb[ng][2], bb[ng][3],
                              stg + PB + s * (16 * 144) + lofsB + ng * 32);
            // hi-term MMAs (8 distinct accs) ...
#pragma unroll
            for (int ng = 0; ng < 4; ng++) {
                MMA_F16(cacc[2 * ng], ah, bb[ng][0], bb[ng][1]);
                MMA_F16(cacc[2 * ng + 1], ah, bb[ng][2], bb[ng][3]);
            }
            // ... lo-term MMAs (RAW distance 8, fp32 accum)
#pragma unroll
            for (int ng = 0; ng < 4; ng++) {
                MMA_F16(cacc[2 * ng], al, bb[ng][0], bb[ng][1]);
                MMA_F16(cacc[2 * ng + 1], al, bb[ng][2], bb[ng][3]);
            }
        }
    }
#undef PROJ_LOAD

    const int g = lane >> 2, tig = lane & 3;
    const size_t obase = (size_t)bh * KP * DK;
#pragma unroll
    for (int nt = 0; nt < 8; nt++) {
        const int row0 = m0k + wm + g;
        const int col = nt * 8 + 2 * tig;
        *(uint32_t*)(O + obase + (size_t)row0 * DK + col) =
            pack_h2(cacc[nt][0], cacc[nt][1]);
        *(uint32_t*)(O + obase + (size_t)(row0 + 8) * DK + col) =
            pack_h2(cacc[nt][2], cacc[nt][3]);
    }
}

// ---------------------------------------------------------------------------
// Fused MMA attention per (bh, 128-row t-tile):
//   S = Q*Kp^T (1-term, fp32 accum)
//   softmax on fragments; ctx = P*Vp (1-term); ctx plain fp16 to Ch.
// ---------------------------------------------------------------------------
#define AQ 0
#define AK (AQ + 128 * 144)
#define AV (AK + 256 * 144)
#define ATTN_SMEM (AV + 256 * 144)      // 92160

__global__ __launch_bounds__(256) void attn_mma(
    const half_t* __restrict__ Q, const half_t* __restrict__ Kp,
    const half_t* __restrict__ Vp, half_t* __restrict__ Ch)
{
    extern __shared__ char smem[];
    const uint32_t sbase = smem_u32(smem);
    const int tid = threadIdx.x, wid = tid >> 5, lane = tid & 31;
    const int bh = blockIdx.y, b = bh >> 4, h = bh & 15;
    const int t0 = blockIdx.x * 128;

    const size_t qbase = (size_t)(b * TT + t0) * DD + h * 64;
    for (int idx = tid; idx < 128 * 8; idx += 256) {
        const int r = idx >> 3, c = idx & 7;
        *(uint4*)(smem + AQ + r * 144 + c * 16) =
            *(const uint4*)(Q + qbase + (size_t)r * DD + c * 8);
    }
    const size_t kpb = (size_t)bh * KP * DK;
    for (int idx = tid; idx < 256 * 8; idx += 256) {
        const int r = idx >> 3, c = idx & 7;
        const size_t go = kpb + (size_t)r * DK + c * 8;
        *(uint4*)(smem + AK + r * 144 + c * 16) = *(const uint4*)(Kp + go);
        *(uint4*)(smem + AV + r * 144 + c * 16) = *(const uint4*)(Vp + go);
    }
    __syncthreads();

    const int wm = wid * 16;
    const uint32_t lofs = (lane & 15) * 144u + ((lane >> 4) * 16u);

    // --- scores (1-term), ng in batches of 4 ---
    float sacc[32][4];
#pragma unroll
    for (int j = 0; j < 32; j++)
#pragma unroll
        for (int q = 0; q < 4; q++) sacc[j][q] = 0.f;

#pragma unroll
    for (int s = 0; s < 4; s++) {
        uint32_t q4[4], bb[4][4];
        LDMATRIX_X4(q4[0], q4[1], q4[2], q4[3], sbase + AQ + wm * 144 + lofs + s * 32);
#pragma unroll
        for (int g4 = 0; g4 < 4; g4++) {
#pragma unroll
            for (int j = 0; j < 4; j++)
                LDMATRIX_X4(bb[j][0], bb[j][1], bb[j][2], bb[j][3],
                            sbase + AK + (g4 * 4 + j) * (16 * 144) + lofs + s * 32);
#pragma unroll
            for (int j = 0; j < 4; j++) {
                const int ng = g4 * 4 + j;
                MMA_F16(sacc[2 * ng], q4, bb[j][0], bb[j][2]);
                MMA_F16(sacc[2 * ng + 1], q4, bb[j][1], bb[j][3]);
            }
        }
    }

    // --- softmax on fragments ---
    float m0 = -1e30f, m1 = -1e30f;
#pragma unroll
    for (int j = 0; j < 32; j++) {
        m0 = fmaxf(m0, fmaxf(sacc[j][0], sacc[j][1]));
        m1 = fmaxf(m1, fmaxf(sacc[j][2], sacc[j][3]));
    }
    m0 = fmaxf(m0, __shfl_xor_sync(0xffffffffu, m0, 1));
    m0 = fmaxf(m0, __shfl_xor_sync(0xffffffffu, m0, 2));
    m1 = fmaxf(m1, __shfl_xor_sync(0xffffffffu, m1, 1));
    m1 = fmaxf(m1, __shfl_xor_sync(0xffffffffu, m1, 2));

    float sum0 = 0.f, sum1 = 0.f;
#pragma unroll
    for (int j = 0; j < 32; j++) {
        float e0 = __expf((sacc[j][0] - m0) * 0.125f);
        float e1 = __expf((sacc[j][1] - m0) * 0.125f);
        float e2 = __expf((sacc[j][2] - m1) * 0.125f);
        float e3 = __expf((sacc[j][3] - m1) * 0.125f);
        sacc[j][0] = e0; sacc[j][1] = e1; sacc[j][2] = e2; sacc[j][3] = e3;
        sum0 += e0 + e1; sum1 += e2 + e3;
    }
    sum0 += __shfl_xor_sync(0xffffffffu, sum0, 1);
    sum0 += __shfl_xor_sync(0xffffffffu, sum0, 2);
    sum1 += __shfl_xor_sync(0xffffffffu, sum1, 1);
    sum1 += __shfl_xor_sync(0xffffffffu, sum1, 2);
    const float inv0 = __frcp_rn(sum0), inv1 = __frcp_rn(sum1);

    // --- ctx = P * Vp (1-term, P plain fp16) ---
    float cacc[8][4];
#pragma unroll
    for (int nt = 0; nt < 8; nt++)
#pragma unroll
        for (int q = 0; q < 4; q++) cacc[nt][q] = 0.f;

#pragma unroll
    for (int s = 0; s < 16; s++) {
        uint32_t ap[4], bb[4][4];
        ap[0] = pack_h2(sacc[2 * s][0],     sacc[2 * s][1]);
        ap[1] = pack_h2(sacc[2 * s][2],     sacc[2 * s][3]);
        ap[2] = pack_h2(sacc[2 * s + 1][0], sacc[2 * s + 1][1]);
        ap[3] = pack_h2(sacc[2 * s + 1][2], sacc[2 * s + 1][3]);
#pragma unroll
        for (int ng = 0; ng < 4; ng++)
            LDMATRIX_X4_T(bb[ng][0], bb[ng][1], bb[ng][2], bb[ng][3],
                          sbase + AV + s * (16 * 144) + lofs + ng * 32);
#pragma unroll
        for (int ng = 0; ng < 4; ng++) {
            MMA_F16(cacc[2 * ng], ap, bb[ng][0], bb[ng][1]);
            MMA_F16(cacc[2 * ng + 1], ap, bb[ng][2], bb[ng][3]);
        }
    }

    // --- epilogue: normalize, write plain fp16 ctx ---
    const int g = lane >> 2, tig = lane & 3;
    const size_t r0 = (size_t)(b * TT + t0 + wm + g) * DD + h * 64;
    const size_t r1 = r0 + 8 * DD;
#pragma unroll
    for (int nt = 0; nt < 8; nt++) {
        const int col = nt * 8 + 2 * tig;
        *(uint32_t*)(Ch + r0 + col) = pack_h2(cacc[nt][0] * inv0, cacc[nt][1] * inv0);
        *(uint32_t*)(Ch + r1 + col) = pack_h2(cacc[nt][2] * inv1, cacc[nt][3] * inv1);
    }
}

// ---------------------------------------------------------------------------
// Launch
// ---------------------------------------------------------------------------
extern "C" void kernel_launch(void* const* d_in, const int* in_sizes, int n_in,
                              void* d_out, int out_size)
{
    const float* x  = (const float*)d_in[0];
    const float* Wq = (const float*)d_in[1];
    const float* Wk = (const float*)d_in[2];
    const float* Wv = (const float*)d_in[3];
    const float* Ek = (const float*)d_in[4];
    const float* Ev = (const float*)d_in[5];
    const float* Wo = (const float*)d_in[6];
    const float* bo = (const float*)d_in[7];
    float* out = (float*)d_out;

    half_t *Ap, *Qp, *Kbp, *Vbp, *Wtp, *Ethp, *Etlp, *Kpp, *Vpp;
    cudaGetSymbolAddress((void**)&Ap,  g_A);
    cudaGetSymbolAddress((void**)&Qp,  g_Q);
    cudaGetSymbolAddress((void**)&Kbp, g_K);
    cudaGetSymbolAddress((void**)&Vbp, g_V);
    cudaGetSymbolAddress((void**)&Wtp, g_Wt);
    cudaGetSymbolAddress((void**)&Ethp, g_Eth);
    cudaGetSymbolAddress((void**)&Etlp, g_Etl);
    cudaGetSymbolAddress((void**)&Kpp, g_Kp);
    cudaGetSymbolAddress((void**)&Vpp, g_Vp);

    const size_t WSZ = (size_t)DD * DD;

    cudaFuncSetAttribute(tc_gemm<1>, cudaFuncAttributeMaxDynamicSharedMemorySize, TC_SMEM);
    cudaFuncSetAttribute(tc_gemm<0>, cudaFuncAttributeMaxDynamicSharedMemorySize, TC_SMEM);
    cudaFuncSetAttribute(proj_mma, cudaFuncAttributeMaxDynamicSharedMemorySize, PROJ_SMEM);
    cudaFuncSetAttribute(attn_mma, cudaFuncAttributeMaxDynamicSharedMemorySize, ATTN_SMEM);

    // 1) convert x -> fp16 plain
    conv_kernel<<<2048, 256>>>(x, Ap, MROWS * DD / 4);
    // 2) transpose+convert weights (plain) + split E
    wconv_kernel<<<dim3(DD / 32, DD / 32, 4), 256>>>(Wq, Wk, Wv, Wo, Wtp);
    esplit_kernel<<<dim3(KP / 32, TT / 32, 2), 256>>>(Ek, Ev, Ethp, Etlp);

    // 3) fused QKV projection (1-term, all-plain outputs)
    tc_gemm<1><<<dim3(3 * DD / 128, MROWS / 128), 256, TC_SMEM>>>(
        Ap, Wtp, nullptr, nullptr, Qp, Kbp, Vbp, DD);

    // 4) low-rank projections (2-term, fp32 accum)
    proj_mma<<<dim3(KP / 128, BHN, 2), 256, PROJ_SMEM>>>(
        Ethp, Etlp, Kbp, Vbp, Kpp, Vpp);

    // 5) fused attention -> ctx plain fp16 into A buffer
    attn_mma<<<dim3(TT / 128, BHN), 256, ATTN_SMEM>>>(
        Qp, Kpp, Vpp, Ap);

    // 6) output projection + bias (1-term, fp32 out)
    tc_gemm<0><<<dim3(DD / 128, MROWS / 128), 256, TC_SMEM>>>(
        Ap, Wtp + 3 * WSZ, out, bo, nullptr, nullptr, nullptr, DD);
}

// round 15
// speedup vs baseline: 2.0527x; 1.3747x over previous
#include <cuda_runtime.h>
#include <cuda_fp16.h>
#include <cstdint>
#include <math.h>

// Problem constants
#define BB 4
#define TT 4096
#define DD 1024
#define HH 16
#define KP 256
#define DK 64
#define MROWS (BB*TT)          // 16384
#define BHN (BB*HH)            // 64

typedef __half half_t;

// ---------------------------------------------------------------------------
// Scratch (static device globals; no allocation allowed)
// ---------------------------------------------------------------------------
__device__ half_t g_A [(size_t)MROWS * DD];      // x plain fp16 (later ctx plain)
__device__ half_t g_Q [(size_t)MROWS * DD];      // plain
__device__ half_t g_Wt[4][(size_t)DD * DD];      // transposed [N][K], plain
__device__ half_t g_Eth[(size_t)2 * KP * TT];    // E^T split hi [z][kp][t]
__device__ half_t g_Etl[(size_t)2 * KP * TT];    // E^T split lo
__device__ half_t g_Xp[(size_t)2 * BB * KP * DD];// xp = E^T x  [z][b][kp][d]
__device__ half_t g_Kp[(size_t)BB * KP * DD];    // Kp [b][kp][d], d = h*64+dk
__device__ half_t g_Vp[(size_t)BB * KP * DD];

// ---------------------------------------------------------------------------
// Helpers
// ---------------------------------------------------------------------------
__device__ __forceinline__ uint32_t smem_u32(const void* p) {
    uint32_t a;
    asm("{ .reg .u64 t; cvta.to.shared.u64 t, %1; cvt.u32.u64 %0, t; }" : "=r"(a) : "l"(p));
    return a;
}

#define CP_ASYNC16(dst, src) \
    asm volatile("cp.async.cg.shared.global [%0], [%1], 16;" :: "r"(dst), "l"(src))
#define CP_COMMIT() asm volatile("cp.async.commit_group;")
#define CP_WAIT1()  asm volatile("cp.async.wait_group 1;" ::: "memory")
#define CP_WAIT0()  asm volatile("cp.async.wait_group 0;" ::: "memory")

#define LDMATRIX_X4(r0, r1, r2, r3, addr) \
    asm volatile("ldmatrix.sync.aligned.m8n8.x4.shared.b16 {%0,%1,%2,%3}, [%4];" \
        : "=r"(r0), "=r"(r1), "=r"(r2), "=r"(r3) : "r"(addr))
#define LDMATRIX_X4_T(r0, r1, r2, r3, addr) \
    asm volatile("ldmatrix.sync.aligned.m8n8.x4.trans.shared.b16 {%0,%1,%2,%3}, [%4];" \
        : "=r"(r0), "=r"(r1), "=r"(r2), "=r"(r3) : "r"(addr))

#define MMA_F16(d, a, b0_, b1_) \
    asm volatile("mma.sync.aligned.m16n8k16.row.col.f32.f16.f16.f32 " \
        "{%0,%1,%2,%3},{%4,%5,%6,%7},{%8,%9},{%0,%1,%2,%3};" \
        : "+f"((d)[0]), "+f"((d)[1]), "+f"((d)[2]), "+f"((d)[3]) \
        : "r"((a)[0]), "r"((a)[1]), "r"((a)[2]), "r"((a)[3]), "r"(b0_), "r"(b1_))

__device__ __forceinline__ uint32_t pack_h2(float a, float b) {
    __half2 t = __floats2half2_rn(a, b);
    return *(uint32_t*)&t;
}

// ---------------------------------------------------------------------------
// Convert fp32 -> fp16 plain (vectorized x4)
// ---------------------------------------------------------------------------
__global__ __launch_bounds__(256) void conv_kernel(
    const float* __restrict__ src, half_t* __restrict__ dst, int n4)
{
    uint32_t* d2 = (uint32_t*)dst;
    int stride = gridDim.x * blockDim.x;
    for (int i = blockIdx.x * blockDim.x + threadIdx.x; i < n4; i += stride) {
        float4 v = ((const float4*)src)[i];
        d2[2 * i + 0] = pack_h2(v.x, v.y);
        d2[2 * i + 1] = pack_h2(v.z, v.w);
    }
}

// Transpose + convert all 4 weights (grid.z selects): [D][D] fp32 -> [N][K] fp16
__global__ __launch_bounds__(256) void wconv_kernel(
    const float* __restrict__ W0, const float* __restrict__ W1,
    const float* __restrict__ W2, const float* __restrict__ W3,
    half_t* __restrict__ WtAll)
{
    __shared__ float t[32][33];
    const int z = blockIdx.z;
    const float* W = (z == 0) ? W0 : (z == 1) ? W1 : (z == 2) ? W2 : W3;
    half_t* Wt = WtAll + (size_t)z * DD * DD;
    const int c0 = blockIdx.x * 32, r0 = blockIdx.y * 32;
    const int tx = threadIdx.x & 31, ty = threadIdx.x >> 5;
#pragma unroll
    for (int r = 0; r < 32; r += 8)
        t[ty + r][tx] = W[(size_t)(r0 + ty + r) * DD + c0 + tx];
    __syncthreads();
#pragma unroll
    for (int r = 0; r < 32; r += 8)
        Wt[(size_t)(c0 + ty + r) * DD + r0 + tx] = __float2half(t[tx][ty + r]);
}

// Transpose + split E (grid.z selects Ek/Ev): [T][KP] fp32 -> [KP][T] fp16 hi/lo
__global__ __launch_bounds__(256) void esplit_kernel(
    const float* __restrict__ E0, const float* __restrict__ E1,
    half_t* __restrict__ hiT, half_t* __restrict__ loT)
{
    __shared__ float t[32][33];
    const int z = blockIdx.z;
    const float* E = z ? E1 : E0;
    half_t* hi = hiT + (size_t)z * KP * TT;
    half_t* lo = loT + (size_t)z * KP * TT;
    const int c0 = blockIdx.x * 32, r0 = blockIdx.y * 32;
    const int tx = threadIdx.x & 31, ty = threadIdx.x >> 5;
#pragma unroll
    for (int r = 0; r < 32; r += 8)
        t[ty + r][tx] = E[(size_t)(r0 + ty + r) * KP + c0 + tx];
    __syncthreads();
#pragma unroll
    for (int r = 0; r < 32; r += 8) {
        float v = t[tx][ty + r];
        half_t h = __float2half(v);
        size_t o = (size_t)(c0 + ty + r) * TT + r0 + tx;
        hi[o] = h;
        lo[o] = __float2half(v - __half2float(h));
    }
}

// ---------------------------------------------------------------------------
// mma.sync fp16 GEMM: C = A[M,K] * B^T   (1-term A, plain everything)
// MODE 0: fp32 out (+bias).
// MODE 1: plain fp16 out to O0.
// MODE 2: z-batched (blockIdx.z): A += z*BB*KP*DD, B += z*DD*DD, O = z?O1:O0.
// Block 128x128, K-chunk 32, 8 warps, 3-stage cp.async pipeline, 2 CTAs/SM.
// ---------------------------------------------------------------------------
#define GTILE   10240                  // 128 rows * 80 B
#define GSTAGE  (2 * GTILE)            // A, B
#define TC_SMEM (3 * GSTAGE)           // 61440

template<int MODE>
__global__ __launch_bounds__(256, 2) void tc_gemm(
    const half_t* __restrict__ Ah, const half_t* __restrict__ Bh,
    float* __restrict__ C, const float* __restrict__ bias,
    half_t* __restrict__ O0, half_t* __restrict__ O1, int Kn)
{
    extern __shared__ char smem[];
    const uint32_t sbase = smem_u32(smem);
    const int tid = threadIdx.x, wid = tid >> 5, lane = tid & 31;
    const int warp_m = wid >> 1, warp_n = wid & 1;
    const int m0 = blockIdx.y * 128;
    const int n0g = blockIdx.x * 128;

    const half_t* A = Ah;
    const half_t* B = Bh;
    half_t* O = O0;
    if (MODE == 2) {
        const int z = blockIdx.z;
        A += (size_t)z * BB * KP * DD;
        B += (size_t)z * DD * DD;
        O = z ? O1 : O0;
    }

    float acc[2][8][4];
#pragma unroll
    for (int mt = 0; mt < 2; mt++)
#pragma unroll
        for (int nt = 0; nt < 8; nt++)
#pragma unroll
            for (int q = 0; q < 4; q++) acc[mt][nt][q] = 0.f;

    const uint32_t lofs = ((((lane >> 3) & 1) * 8 + (lane & 7)) * 80u) + ((lane >> 4) * 16u);
    const int ld_row0 = tid >> 2;
    const int ld_col  = tid & 3;

    const int NC = Kn >> 5;
#define LOAD_STAGE(s, k0v) do {                                                   \
        const uint32_t stg = sbase + (uint32_t)(s) * GSTAGE;                      \
        _Pragma("unroll")                                                         \
        for (int i = 0; i < 4; i++) {                                             \
            const int t = i >> 1;                                                 \
            const int row = (i & 1) * 64 + ld_row0;                               \
            const half_t* sp = (t == 0 ? A : B);                                  \
            const int grow = (t == 0 ? m0 : n0g) + row;                           \
            CP_ASYNC16(stg + t * GTILE + row * 80 + ld_col * 16,                  \
                       sp + (size_t)grow * Kn + (k0v) + ld_col * 8);              \
        }                                                                         \
        CP_COMMIT();                                                              \
    } while (0)

    LOAD_STAGE(0, 0);
    LOAD_STAGE(1, 32);

    for (int c = 0; c < NC; c++) {
        const bool more = (c + 2 < NC);
        if (more) { CP_WAIT1(); } else { CP_WAIT0(); }   // tail: full drain
        __syncthreads();
        if (more) LOAD_STAGE((c + 2) % 3, (c + 2) << 5);

        const uint32_t stg = sbase + (uint32_t)(c % 3) * GSTAGE;
        const uint32_t a_base = stg + (warp_m * 32) * 80 + lofs;
        const uint32_t b_base = stg + GTILE + (warp_n * 64) * 80 + lofs;

#pragma unroll
        for (int ks = 0; ks < 2; ks++) {
            uint32_t ah[2][4], b[4][4];
#pragma unroll
            for (int mt = 0; mt < 2; mt++)
                LDMATRIX_X4(ah[mt][0], ah[mt][1], ah[mt][2], ah[mt][3],
                            a_base + mt * (16 * 80) + ks * 32);
#pragma unroll
            for (int nq = 0; nq < 4; nq++)
                LDMATRIX_X4(b[nq][0], b[nq][1], b[nq][2], b[nq][3],
                            b_base + nq * (16 * 80) + ks * 32);
#pragma unroll
            for (int mt = 0; mt < 2; mt++)
#pragma unroll
                for (int nt = 0; nt < 8; nt++) {
                    const int nq = nt >> 1, sel = nt & 1;
                    MMA_F16(acc[mt][nt], ah[mt], b[nq][sel], b[nq][sel + 2]);
                }
        }
    }
#undef LOAD_STAGE

    const int g = lane >> 2, tig = lane & 3;
#pragma unroll
    for (int mt = 0; mt < 2; mt++) {
        const int row0 = m0 + warp_m * 32 + mt * 16 + g;
#pragma unroll
        for (int nt = 0; nt < 8; nt++) {
            const int colg = n0g + warp_n * 64 + nt * 8 + 2 * tig;
            if (MODE == 0) {
                float bx = 0.f, by = 0.f;
                if (bias) { bx = bias[colg]; by = bias[colg + 1]; }
                *(float2*)(C + (size_t)row0 * DD + colg) =
                    make_float2(acc[mt][nt][0] + bx, acc[mt][nt][1] + by);
                *(float2*)(C + (size_t)(row0 + 8) * DD + colg) =
                    make_float2(acc[mt][nt][2] + bx, acc[mt][nt][3] + by);
            } else {
                const size_t o0 = (size_t)row0 * DD + colg;
                const size_t o1 = (size_t)(row0 + 8) * DD + colg;
                *(uint32_t*)(O + o0) = pack_h2(acc[mt][nt][0], acc[mt][nt][1]);
                *(uint32_t*)(O + o1) = pack_h2(acc[mt][nt][2], acc[mt][nt][3]);
            }
        }
    }
}

// ---------------------------------------------------------------------------
// xp = E^T x  (2-term E split, fp32 accum), 3-stage pipeline:
//   xp[z][b][kp][d-slab] = sum_t (Eh+El)[z][kp][t] * x[b][t][n64*64 + d]
// grid = (KP/128, BB*16, 2): blockIdx.y = b*16 + n64
// ---------------------------------------------------------------------------
#define PAH 0
#define PALo 10240
#define PB  20480
#define PSTAGE (PB + 32 * 144)          // 25088
#define PROJ_SMEM (3 * PSTAGE)          // 75264

__global__ __launch_bounds__(256) void xp_mma(
    const half_t* __restrict__ Eh, const half_t* __restrict__ El,
    const half_t* __restrict__ X, half_t* __restrict__ Xp)
{
    extern __shared__ char smem[];
    const uint32_t sbase = smem_u32(smem);
    const int tid = threadIdx.x, wid = tid >> 5, lane = tid & 31;
    const int m0k = blockIdx.x * 128;
    const int b = blockIdx.y >> 4, n64 = blockIdx.y & 15;
    const int z = blockIdx.z;

    const size_t eoff = (size_t)z * KP * TT;
    const size_t brow = (size_t)b * TT;
    const int hcol = n64 * 64;
    half_t* O = Xp + (size_t)z * BB * KP * DD + (size_t)b * KP * DD;

    float cacc[8][4];
#pragma unroll
    for (int nt = 0; nt < 8; nt++)
#pragma unroll
        for (int q = 0; q < 4; q++) cacc[nt][q] = 0.f;

    const uint32_t lofsA = (lane & 15) * 80u + ((lane >> 4) * 16u);
    const uint32_t lofsB = (lane & 15) * 144u + ((lane >> 4) * 16u);
    const int wm = wid * 16;

#define PROJ_LOAD(s, k0v) do {                                                    \
        const uint32_t stg = sbase + (uint32_t)(s) * PSTAGE;                      \
        _Pragma("unroll")                                                         \
        for (int i = 0; i < 2; i++) {                                             \
            const int idx = tid + i * 256;                                        \
            const int r = idx >> 2, cc = idx & 3;                                 \
            const size_t gof = (size_t)(m0k + r) * TT + (k0v) + cc * 8;           \
            CP_ASYNC16(stg + PAH + r * 80 + cc * 16, Eh + eoff + gof);            \
            CP_ASYNC16(stg + PALo + r * 80 + cc * 16, El + eoff + gof);           \
        }                                                                         \
        {                                                                         \
            const int r = tid >> 3, cc = tid & 7;                                 \
            const size_t gof = (brow + (k0v) + r) * DD + hcol + cc * 8;           \
            CP_ASYNC16(stg + PB + r * 144 + cc * 16, X + gof);                    \
        }                                                                         \
        CP_COMMIT();                                                              \
    } while (0)

    PROJ_LOAD(0, 0);
    PROJ_LOAD(1, 32);
    const int NC = TT >> 5;
    for (int c = 0; c < NC; c++) {
        const bool more = (c + 2 < NC);
        if (more) { CP_WAIT1(); } else { CP_WAIT0(); }   // tail: full drain
        __syncthreads();
        if (more) PROJ_LOAD((c + 2) % 3, (c + 2) << 5);

        const uint32_t stg = sbase + (uint32_t)(c % 3) * PSTAGE;
#pragma unroll
        for (int s = 0; s < 2; s++) {
            uint32_t ah[4], al[4], bb[4][4];
            LDMATRIX_X4(ah[0], ah[1], ah[2], ah[3], stg + PAH + wm * 80 + lofsA + s * 32);
            LDMATRIX_X4(al[0], al[1], al[2], al[3], stg + PALo + wm * 80 + lofsA + s * 32);
#pragma unroll
            for (int ng = 0; ng < 4; ng++)
                LDMATRIX_X4_T(bb[ng][0], bb[ng][1], bb[ng][2], bb[ng][3],
                              stg + PB + s * (16 * 144) + lofsB + ng * 32);
#pragma unroll
            for (int ng = 0; ng < 4; ng++) {
                MMA_F16(cacc[2 * ng], ah, bb[ng][0], bb[ng][1]);
                MMA_F16(cacc[2 * ng + 1], ah, bb[ng][2], bb[ng][3]);
            }
#pragma unroll
            for (int ng = 0; ng < 4; ng++) {
                MMA_F16(cacc[2 * ng], al, bb[ng][0], bb[ng][1]);
                MMA_F16(cacc[2 * ng + 1], al, bb[ng][2], bb[ng][3]);
            }
        }
    }
#undef PROJ_LOAD

    const int g = lane >> 2, tig = lane & 3;
#pragma unroll
    for (int nt = 0; nt < 8; nt++) {
        const int row0 = m0k + wm + g;
        const int col = hcol + nt * 8 + 2 * tig;
        *(uint32_t*)(O + (size_t)row0 * DD + col) =
            pack_h2(cacc[nt][0], cacc[nt][1]);
        *(uint32_t*)(O + (size_t)(row0 + 8) * DD + col) =
            pack_h2(cacc[nt][2], cacc[nt][3]);
    }
}

// ---------------------------------------------------------------------------
// Fused MMA attention per (bh, 128-row t-tile):
//   S = Q*Kp^T (1-term, fp32 accum), softmax, ctx = P*Vp; ctx plain to Ch.
// Kp/Vp layout: [b][kp][DD] with head at column h*64.
// ---------------------------------------------------------------------------
#define AQ 0
#define AK (AQ + 128 * 144)
#define AV (AK + 256 * 144)
#define ATTN_SMEM (AV + 256 * 144)      // 92160

__global__ __launch_bounds__(256) void attn_mma(
    const half_t* __restrict__ Q, const half_t* __restrict__ Kp,
    const half_t* __restrict__ Vp, half_t* __restrict__ Ch)
{
    extern __shared__ char smem[];
    const uint32_t sbase = smem_u32(smem);
    const int tid = threadIdx.x, wid = tid >> 5, lane = tid & 31;
    const int bh = blockIdx.y, b = bh >> 4, h = bh & 15;
    const int t0 = blockIdx.x * 128;

    const size_t qbase = (size_t)(b * TT + t0) * DD + h * 64;
    for (int idx = tid; idx < 128 * 8; idx += 256) {
        const int r = idx >> 3, c = idx & 7;
        *(uint4*)(smem + AQ + r * 144 + c * 16) =
            *(const uint4*)(Q + qbase + (size_t)r * DD + c * 8);
    }
    const size_t kpb = (size_t)b * KP * DD + h * 64;
    for (int idx = tid; idx < 256 * 8; idx += 256) {
        const int r = idx >> 3, c = idx & 7;
        const size_t go = kpb + (size_t)r * DD + c * 8;
        *(uint4*)(smem + AK + r * 144 + c * 16) = *(const uint4*)(Kp + go);
        *(uint4*)(smem + AV + r * 144 + c * 16) = *(const uint4*)(Vp + go);
    }
    __syncthreads();

    const int wm = wid * 16;
    const uint32_t lofs = (lane & 15) * 144u + ((lane >> 4) * 16u);

    // --- scores (1-term), ng in batches of 4 ---
    float sacc[32][4];
#pragma unroll
    for (int j = 0; j < 32; j++)
#pragma unroll
        for (int q = 0; q < 4; q++) sacc[j][q] = 0.f;

#pragma unroll
    for (int s = 0; s < 4; s++) {
        uint32_t q4[4], bb[4][4];
        LDMATRIX_X4(q4[0], q4[1], q4[2], q4[3], sbase + AQ + wm * 144 + lofs + s * 32);
#pragma unroll
        for (int g4 = 0; g4 < 4; g4++) {
#pragma unroll
            for (int j = 0; j < 4; j++)
                LDMATRIX_X4(bb[j][0], bb[j][1], bb[j][2], bb[j][3],
                            sbase + AK + (g4 * 4 + j) * (16 * 144) + lofs + s * 32);
#pragma unroll
            for (int j = 0; j < 4; j++) {
                const int ng = g4 * 4 + j;
                MMA_F16(sacc[2 * ng], q4, bb[j][0], bb[j][2]);
                MMA_F16(sacc[2 * ng + 1], q4, bb[j][1], bb[j][3]);
            }
        }
    }

    // --- softmax on fragments ---
    float m0 = -1e30f, m1 = -1e30f;
#pragma unroll
    for (int j = 0; j < 32; j++) {
        m0 = fmaxf(m0, fmaxf(sacc[j][0], sacc[j][1]));
        m1 = fmaxf(m1, fmaxf(sacc[j][2], sacc[j][3]));
    }
    m0 = fmaxf(m0, __shfl_xor_sync(0xffffffffu, m0, 1));
    m0 = fmaxf(m0, __shfl_xor_sync(0xffffffffu, m0, 2));
    m1 = fmaxf(m1, __shfl_xor_sync(0xffffffffu, m1, 1));
    m1 = fmaxf(m1, __shfl_xor_sync(0xffffffffu, m1, 2));

    float sum0 = 0.f, sum1 = 0.f;
#pragma unroll
    for (int j = 0; j < 32; j++) {
        float e0 = __expf((sacc[j][0] - m0) * 0.125f);
        float e1 = __expf((sacc[j][1] - m0) * 0.125f);
        float e2 = __expf((sacc[j][2] - m1) * 0.125f);
        float e3 = __expf((sacc[j][3] - m1) * 0.125f);
        sacc[j][0] = e0; sacc[j][1] = e1; sacc[j][2] = e2; sacc[j][3] = e3;
        sum0 += e0 + e1; sum1 += e2 + e3;
    }
    sum0 += __shfl_xor_sync(0xffffffffu, sum0, 1);
    sum0 += __shfl_xor_sync(0xffffffffu, sum0, 2);
    sum1 += __shfl_xor_sync(0xffffffffu, sum1, 1);
    sum1 += __shfl_xor_sync(0xffffffffu, sum1, 2);
    const float inv0 = __frcp_rn(sum0), inv1 = __frcp_rn(sum1);

    // --- ctx = P * Vp (1-term, P plain fp16) ---
    float cacc[8][4];
#pragma unroll
    for (int nt = 0; nt < 8; nt++)
#pragma unroll
        for (int q = 0; q < 4; q++) cacc[nt][q] = 0.f;

#pragma unroll
    for (int s = 0; s < 16; s++) {
        uint32_t ap[4], bb[4][4];
        ap[0] = pack_h2(sacc[2 * s][0],     sacc[2 * s][1]);
        ap[1] = pack_h2(sacc[2 * s][2],     sacc[2 * s][3]);
        ap[2] = pack_h2(sacc[2 * s + 1][0], sacc[2 * s + 1][1]);
        ap[3] = pack_h2(sacc[2 * s + 1][2], sacc[2 * s + 1][3]);
#pragma unroll
        for (int ng = 0; ng < 4; ng++)
            LDMATRIX_X4_T(bb[ng][0], bb[ng][1], bb[ng][2], bb[ng][3],
                          sbase + AV + s * (16 * 144) + lofs + ng * 32);
#pragma unroll
        for (int ng = 0; ng < 4; ng++) {
            MMA_F16(cacc[2 * ng], ap, bb[ng][0], bb[ng][1]);
            MMA_F16(cacc[2 * ng + 1], ap, bb[ng][2], bb[ng][3]);
        }
    }

    // --- epilogue: normalize, write plain fp16 ctx ---
    const int g = lane >> 2, tig = lane & 3;
    const size_t r0 = (size_t)(b * TT + t0 + wm + g) * DD + h * 64;
    const size_t r1 = r0 + 8 * DD;
#pragma unroll
    for (int nt = 0; nt < 8; nt++) {
        const int col = nt * 8 + 2 * tig;
        *(uint32_t*)(Ch + r0 + col) = pack_h2(cacc[nt][0] * inv0, cacc[nt][1] * inv0);
        *(uint32_t*)(Ch + r1 + col) = pack_h2(cacc[nt][2] * inv1, cacc[nt][3] * inv1);
    }
}

// ---------------------------------------------------------------------------
// Launch
// ---------------------------------------------------------------------------
extern "C" void kernel_launch(void* const* d_in, const int* in_sizes, int n_in,
                              void* d_out, int out_size)
{
    const float* x  = (const float*)d_in[0];
    const float* Wq = (const float*)d_in[1];
    const float* Wk = (const float*)d_in[2];
    const float* Wv = (const float*)d_in[3];
    const float* Ek = (const float*)d_in[4];
    const float* Ev = (const float*)d_in[5];
    const float* Wo = (const float*)d_in[6];
    const float* bo = (const float*)d_in[7];
    float* out = (float*)d_out;

    half_t *Ap, *Qp, *Wtp, *Ethp, *Etlp, *Xpp, *Kpp, *Vpp;
    cudaGetSymbolAddress((void**)&Ap,  g_A);
    cudaGetSymbolAddress((void**)&Qp,  g_Q);
    cudaGetSymbolAddress((void**)&Wtp, g_Wt);
    cudaGetSymbolAddress((void**)&Ethp, g_Eth);
    cudaGetSymbolAddress((void**)&Etlp, g_Etl);
    cudaGetSymbolAddress((void**)&Xpp, g_Xp);
    cudaGetSymbolAddress((void**)&Kpp, g_Kp);
    cudaGetSymbolAddress((void**)&Vpp, g_Vp);

    const size_t WSZ = (size_t)DD * DD;

    cudaFuncSetAttribute(tc_gemm<0>, cudaFuncAttributeMaxDynamicSharedMemorySize, TC_SMEM);
    cudaFuncSetAttribute(tc_gemm<1>, cudaFuncAttributeMaxDynamicSharedMemorySize, TC_SMEM);
    cudaFuncSetAttribute(tc_gemm<2>, cudaFuncAttributeMaxDynamicSharedMemorySize, TC_SMEM);
    cudaFuncSetAttribute(xp_mma, cudaFuncAttributeMaxDynamicSharedMemorySize, PROJ_SMEM);
    cudaFuncSetAttribute(attn_mma, cudaFuncAttributeMaxDynamicSharedMemorySize, ATTN_SMEM);

    // 1) convert x -> fp16 plain
    conv_kernel<<<2048, 256>>>(x, Ap, MROWS * DD / 4);
    // 2) transpose+convert weights (plain) + split E
    wconv_kernel<<<dim3(DD / 32, DD / 32, 4), 256>>>(Wq, Wk, Wv, Wo, Wtp);
    esplit_kernel<<<dim3(KP / 32, TT / 32, 2), 256>>>(Ek, Ev, Ethp, Etlp);

    // 3) xp = E^T x  (both z) — independent of Q GEMM
    xp_mma<<<dim3(KP / 128, BB * 16, 2), 256, PROJ_SMEM>>>(Ethp, Etlp, Ap, Xpp);

    // 4) Q = x * Wq (plain fp16 out)
    tc_gemm<1><<<dim3(DD / 128, MROWS / 128), 256, TC_SMEM>>>(
        Ap, Wtp, nullptr, nullptr, Qp, nullptr, DD);

    // 5) Kp = xp_k * Wk, Vp = xp_v * Wv (z-batched small GEMMs)
    tc_gemm<2><<<dim3(DD / 128, (BB * KP) / 128, 2), 256, TC_SMEM>>>(
        Xpp, Wtp + 1 * WSZ, nullptr, nullptr, Kpp, Vpp, DD);

    // 6) fused attention -> ctx plain fp16 into A buffer
    attn_mma<<<dim3(TT / 128, BHN), 256, ATTN_SMEM>>>(Qp, Kpp, Vpp, Ap);

    // 7) output projection + bias (fp32 out)
    tc_gemm<0><<<dim3(DD / 128, MROWS / 128), 256, TC_SMEM>>>(
        Ap, Wtp + 3 * WSZ, out, bo, nullptr, nullptr, DD);
}

// round 16
// speedup vs baseline: 2.4289x; 1.1833x over previous
#include <cuda_runtime.h>
#include <cuda_fp16.h>
#include <cstdint>
#include <math.h>

// Problem constants
#define BB 4
#define TT 4096
#define DD 1024
#define HH 16
#define KP 256
#define DK 64
#define MROWS (BB*TT)          // 16384
#define BHN (BB*HH)            // 64

typedef __half half_t;

// ---------------------------------------------------------------------------
// Scratch (static device globals; no allocation allowed)
// ---------------------------------------------------------------------------
__device__ half_t g_A [(size_t)MROWS * DD];      // x plain fp16 (later ctx plain)
__device__ half_t g_Q [(size_t)MROWS * DD];      // plain
__device__ half_t g_Wt[4][(size_t)DD * DD];      // transposed [N][K], plain
__device__ half_t g_Eth[(size_t)2 * KP * TT];    // E^T split hi [z][kp][t]
__device__ half_t g_Etl[(size_t)2 * KP * TT];    // E^T split lo
__device__ half_t g_Xp[(size_t)2 * BB * KP * DD];// xp = E^T x  [z][b][kp][d]
__device__ half_t g_Kp[(size_t)BB * KP * DD];    // Kp [b][kp][d], d = h*64+dk
__device__ half_t g_Vp[(size_t)BB * KP * DD];

// ---------------------------------------------------------------------------
// Helpers
// ---------------------------------------------------------------------------
__device__ __forceinline__ uint32_t smem_u32(const void* p) {
    uint32_t a;
    asm("{ .reg .u64 t; cvta.to.shared.u64 t, %1; cvt.u32.u64 %0, t; }" : "=r"(a) : "l"(p));
    return a;
}

#define CP_ASYNC16(dst, src) \
    asm volatile("cp.async.cg.shared.global [%0], [%1], 16;" :: "r"(dst), "l"(src))
#define CP_COMMIT() asm volatile("cp.async.commit_group;")
#define CP_WAIT1()  asm volatile("cp.async.wait_group 1;" ::: "memory")
#define CP_WAIT0()  asm volatile("cp.async.wait_group 0;" ::: "memory")

#define LDMATRIX_X4(r0, r1, r2, r3, addr) \
    asm volatile("ldmatrix.sync.aligned.m8n8.x4.shared.b16 {%0,%1,%2,%3}, [%4];" \
        : "=r"(r0), "=r"(r1), "=r"(r2), "=r"(r3) : "r"(addr))
#define LDMATRIX_X4_T(r0, r1, r2, r3, addr) \
    asm volatile("ldmatrix.sync.aligned.m8n8.x4.trans.shared.b16 {%0,%1,%2,%3}, [%4];" \
        : "=r"(r0), "=r"(r1), "=r"(r2), "=r"(r3) : "r"(addr))

#define MMA_F16(d, a, b0_, b1_) \
    asm volatile("mma.sync.aligned.m16n8k16.row.col.f32.f16.f16.f32 " \
        "{%0,%1,%2,%3},{%4,%5,%6,%7},{%8,%9},{%0,%1,%2,%3};" \
        : "+f"((d)[0]), "+f"((d)[1]), "+f"((d)[2]), "+f"((d)[3]) \
        : "r"((a)[0]), "r"((a)[1]), "r"((a)[2]), "r"((a)[3]), "r"(b0_), "r"(b1_))

__device__ __forceinline__ uint32_t pack_h2(float a, float b) {
    __half2 t = __floats2half2_rn(a, b);
    return *(uint32_t*)&t;
}

// ---------------------------------------------------------------------------
// Convert fp32 -> fp16 plain (vectorized x4)
// ---------------------------------------------------------------------------
__global__ __launch_bounds__(256) void conv_kernel(
    const float* __restrict__ src, half_t* __restrict__ dst, int n4)
{
    uint32_t* d2 = (uint32_t*)dst;
    int stride = gridDim.x * blockDim.x;
    for (int i = blockIdx.x * blockDim.x + threadIdx.x; i < n4; i += stride) {
        float4 v = ((const float4*)src)[i];
        d2[2 * i + 0] = pack_h2(v.x, v.y);
        d2[2 * i + 1] = pack_h2(v.z, v.w);
    }
}

// Transpose + convert all 4 weights (grid.z selects): [D][D] fp32 -> [N][K] fp16
__global__ __launch_bounds__(256) void wconv_kernel(
    const float* __restrict__ W0, const float* __restrict__ W1,
    const float* __restrict__ W2, const float* __restrict__ W3,
    half_t* __restrict__ WtAll)
{
    __shared__ float t[32][33];
    const int z = blockIdx.z;
    const float* W = (z == 0) ? W0 : (z == 1) ? W1 : (z == 2) ? W2 : W3;
    half_t* Wt = WtAll + (size_t)z * DD * DD;
    const int c0 = blockIdx.x * 32, r0 = blockIdx.y * 32;
    const int tx = threadIdx.x & 31, ty = threadIdx.x >> 5;
#pragma unroll
    for (int r = 0; r < 32; r += 8)
        t[ty + r][tx] = W[(size_t)(r0 + ty + r) * DD + c0 + tx];
    __syncthreads();
#pragma unroll
    for (int r = 0; r < 32; r += 8)
        Wt[(size_t)(c0 + ty + r) * DD + r0 + tx] = __float2half(t[tx][ty + r]);
}

// Transpose + split E (grid.z selects Ek/Ev): [T][KP] fp32 -> [KP][T] fp16 hi/lo
__global__ __launch_bounds__(256) void esplit_kernel(
    const float* __restrict__ E0, const float* __restrict__ E1,
    half_t* __restrict__ hiT, half_t* __restrict__ loT)
{
    __shared__ float t[32][33];
    const int z = blockIdx.z;
    const float* E = z ? E1 : E0;
    half_t* hi = hiT + (size_t)z * KP * TT;
    half_t* lo = loT + (size_t)z * KP * TT;
    const int c0 = blockIdx.x * 32, r0 = blockIdx.y * 32;
    const int tx = threadIdx.x & 31, ty = threadIdx.x >> 5;
#pragma unroll
    for (int r = 0; r < 32; r += 8)
        t[ty + r][tx] = E[(size_t)(r0 + ty + r) * KP + c0 + tx];
    __syncthreads();
#pragma unroll
    for (int r = 0; r < 32; r += 8) {
        float v = t[tx][ty + r];
        half_t h = __float2half(v);
        size_t o = (size_t)(c0 + ty + r) * TT + r0 + tx;
        hi[o] = h;
        lo[o] = __float2half(v - __half2float(h));
    }
}

// ---------------------------------------------------------------------------
// GEMM tile constants
// ---------------------------------------------------------------------------
#define GTILE   10240                  // 128 rows * 80 B
#define GSTAGE  (2 * GTILE)            // A, B
#define TC_SMEM (3 * GSTAGE)           // 61440

#define PAH 0
#define PALo 10240
#define PB  20480
#define PSTAGE (PB + 32 * 144)          // 25088
#define PROJ_SMEM (3 * PSTAGE)          // 75264
#define FUSED_SMEM PROJ_SMEM            // max(61440, 75264)

// ---------------------------------------------------------------------------
// GEMM device body (1-term A, plain B). MODE 0: fp32 out (+bias); else fp16.
// ---------------------------------------------------------------------------
template<int MODE>
__device__ __forceinline__ void gemm_body(
    char* smem, const half_t* __restrict__ A, const half_t* __restrict__ B,
    float* __restrict__ C, const float* __restrict__ bias,
    half_t* __restrict__ O, int m0, int n0g, int Kn)
{
    const uint32_t sbase = smem_u32(smem);
    const int tid = threadIdx.x, wid = tid >> 5, lane = tid & 31;
    const int warp_m = wid >> 1, warp_n = wid & 1;

    float acc[2][8][4];
#pragma unroll
    for (int mt = 0; mt < 2; mt++)
#pragma unroll
        for (int nt = 0; nt < 8; nt++)
#pragma unroll
            for (int q = 0; q < 4; q++) acc[mt][nt][q] = 0.f;

    const uint32_t lofs = ((((lane >> 3) & 1) * 8 + (lane & 7)) * 80u) + ((lane >> 4) * 16u);
    const int ld_row0 = tid >> 2;
    const int ld_col  = tid & 3;

    const int NC = Kn >> 5;
#define LOAD_STAGE(s, k0v) do {                                                   \
        const uint32_t stg = sbase + (uint32_t)(s) * GSTAGE;                      \
        _Pragma("unroll")                                                         \
        for (int i = 0; i < 4; i++) {                                             \
            const int t = i >> 1;                                                 \
            const int row = (i & 1) * 64 + ld_row0;                               \
            const half_t* sp = (t == 0 ? A : B);                                  \
            const int grow = (t == 0 ? m0 : n0g) + row;                           \
            CP_ASYNC16(stg + t * GTILE + row * 80 + ld_col * 16,                  \
                       sp + (size_t)grow * Kn + (k0v) + ld_col * 8);              \
        }                                                                         \
        CP_COMMIT();                                                              \
    } while (0)

    LOAD_STAGE(0, 0);
    LOAD_STAGE(1, 32);

    for (int c = 0; c < NC; c++) {
        const bool more = (c + 2 < NC);
        if (more) { CP_WAIT1(); } else { CP_WAIT0(); }   // tail: full drain
        __syncthreads();
        if (more) LOAD_STAGE((c + 2) % 3, (c + 2) << 5);

        const uint32_t stg = sbase + (uint32_t)(c % 3) * GSTAGE;
        const uint32_t a_base = stg + (warp_m * 32) * 80 + lofs;
        const uint32_t b_base = stg + GTILE + (warp_n * 64) * 80 + lofs;

#pragma unroll
        for (int ks = 0; ks < 2; ks++) {
            uint32_t ah[2][4], b[4][4];
#pragma unroll
            for (int mt = 0; mt < 2; mt++)
                LDMATRIX_X4(ah[mt][0], ah[mt][1], ah[mt][2], ah[mt][3],
                            a_base + mt * (16 * 80) + ks * 32);
#pragma unroll
            for (int nq = 0; nq < 4; nq++)
                LDMATRIX_X4(b[nq][0], b[nq][1], b[nq][2], b[nq][3],
                            b_base + nq * (16 * 80) + ks * 32);
#pragma unroll
            for (int mt = 0; mt < 2; mt++)
#pragma unroll
                for (int nt = 0; nt < 8; nt++) {
                    const int nq = nt >> 1, sel = nt & 1;
                    MMA_F16(acc[mt][nt], ah[mt], b[nq][sel], b[nq][sel + 2]);
                }
        }
    }
#undef LOAD_STAGE

    const int g = lane >> 2, tig = lane & 3;
#pragma unroll
    for (int mt = 0; mt < 2; mt++) {
        const int row0 = m0 + warp_m * 32 + mt * 16 + g;
#pragma unroll
        for (int nt = 0; nt < 8; nt++) {
            const int colg = n0g + warp_n * 64 + nt * 8 + 2 * tig;
            if (MODE == 0) {
                float bx = bias[colg], by = bias[colg + 1];
                *(float2*)(C + (size_t)row0 * DD + colg) =
                    make_float2(acc[mt][nt][0] + bx, acc[mt][nt][1] + by);
                *(float2*)(C + (size_t)(row0 + 8) * DD + colg) =
                    make_float2(acc[mt][nt][2] + bx, acc[mt][nt][3] + by);
            } else {
                const size_t o0 = (size_t)row0 * DD + colg;
                const size_t o1 = (size_t)(row0 + 8) * DD + colg;
                *(uint32_t*)(O + o0) = pack_h2(acc[mt][nt][0], acc[mt][nt][1]);
                *(uint32_t*)(O + o1) = pack_h2(acc[mt][nt][2], acc[mt][nt][3]);
            }
        }
    }
}

// ---------------------------------------------------------------------------
// xp device body: xp = E^T x  (2-term E split, fp32 accum)
// ---------------------------------------------------------------------------
__device__ __forceinline__ void xp_body(
    char* smem, const half_t* __restrict__ Eh, const half_t* __restrict__ El,
    const half_t* __restrict__ X, half_t* __restrict__ Xp,
    int m0k, int b, int n64, int z)
{
    const uint32_t sbase = smem_u32(smem);
    const int tid = threadIdx.x, wid = tid >> 5, lane = tid & 31;

    const size_t eoff = (size_t)z * KP * TT;
    const size_t brow = (size_t)b * TT;
    const int hcol = n64 * 64;
    half_t* O = Xp + (size_t)z * BB * KP * DD + (size_t)b * KP * DD;

    float cacc[8][4];
#pragma unroll
    for (int nt = 0; nt < 8; nt++)
#pragma unroll
        for (int q = 0; q < 4; q++) cacc[nt][q] = 0.f;

    const uint32_t lofsA = (lane & 15) * 80u + ((lane >> 4) * 16u);
    const uint32_t lofsB = (lane & 15) * 144u + ((lane >> 4) * 16u);
    const int wm = wid * 16;

#define PROJ_LOAD(s, k0v) do {                                                    \
        const uint32_t stg = sbase + (uint32_t)(s) * PSTAGE;                      \
        _Pragma("unroll")                                                         \
        for (int i = 0; i < 2; i++) {                                             \
            const int idx = tid + i * 256;                                        \
            const int r = idx >> 2, cc = idx & 3;                                 \
            const size_t gof = (size_t)(m0k + r) * TT + (k0v) + cc * 8;           \
            CP_ASYNC16(stg + PAH + r * 80 + cc * 16, Eh + eoff + gof);            \
            CP_ASYNC16(stg + PALo + r * 80 + cc * 16, El + eoff + gof);           \
        }                                                                         \
        {                                                                         \
            const int r = tid >> 3, cc = tid & 7;                                 \
            const size_t gof = (brow + (k0v) + r) * DD + hcol + cc * 8;           \
            CP_ASYNC16(stg + PB + r * 144 + cc * 16, X + gof);                    \
        }                                                                         \
        CP_COMMIT();                                                              \
    } while (0)

    PROJ_LOAD(0, 0);
    PROJ_LOAD(1, 32);
    const int NC = TT >> 5;
    for (int c = 0; c < NC; c++) {
        const bool more = (c + 2 < NC);
        if (more) { CP_WAIT1(); } else { CP_WAIT0(); }   // tail: full drain
        __syncthreads();
        if (more) PROJ_LOAD((c + 2) % 3, (c + 2) << 5);

        const uint32_t stg = sbase + (uint32_t)(c % 3) * PSTAGE;
#pragma unroll
        for (int s = 0; s < 2; s++) {
            uint32_t ah[4], al[4], bb[4][4];
            LDMATRIX_X4(ah[0], ah[1], ah[2], ah[3], stg + PAH + wm * 80 + lofsA + s * 32);
            LDMATRIX_X4(al[0], al[1], al[2], al[3], stg + PALo + wm * 80 + lofsA + s * 32);
#pragma unroll
            for (int ng = 0; ng < 4; ng++)
                LDMATRIX_X4_T(bb[ng][0], bb[ng][1], bb[ng][2], bb[ng][3],
                              stg + PB + s * (16 * 144) + lofsB + ng * 32);
#pragma unroll
            for (int ng = 0; ng < 4; ng++) {
                MMA_F16(cacc[2 * ng], ah, bb[ng][0], bb[ng][1]);
                MMA_F16(cacc[2 * ng + 1], ah, bb[ng][2], bb[ng][3]);
            }
#pragma unroll
            for (int ng = 0; ng < 4; ng++) {
                MMA_F16(cacc[2 * ng], al, bb[ng][0], bb[ng][1]);
                MMA_F16(cacc[2 * ng + 1], al, bb[ng][2], bb[ng][3]);
            }
        }
    }
#undef PROJ_LOAD

    const int g = lane >> 2, tig = lane & 3;
#pragma unroll
    for (int nt = 0; nt < 8; nt++) {
        const int row0 = m0k + wm + g;
        const int col = hcol + nt * 8 + 2 * tig;
        *(uint32_t*)(O + (size_t)row0 * DD + col) =
            pack_h2(cacc[nt][0], cacc[nt][1]);
        *(uint32_t*)(O + (size_t)(row0 + 8) * DD + col) =
            pack_h2(cacc[nt][2], cacc[nt][3]);
    }
}

// ---------------------------------------------------------------------------
// Fused launch: blocks [0,256) run xp (scheduled first), [256,1280) run Q GEMM.
// ---------------------------------------------------------------------------
__global__ __launch_bounds__(256, 2) void fused_xpq(
    const half_t* __restrict__ Eh, const half_t* __restrict__ El,
    const half_t* __restrict__ X, half_t* __restrict__ Xp,
    const half_t* __restrict__ Wq, half_t* __restrict__ Q)
{
    extern __shared__ char smem[];
    const int bid = blockIdx.x;
    if (bid < 256) {
        const int m0k = (bid & 1) * 128;
        const int y = (bid >> 1) & 63;
        const int z = bid >> 7;
        xp_body(smem, Eh, El, X, Xp, m0k, y >> 4, y & 15, z);
    } else {
        const int q = bid - 256;
        gemm_body<1>(smem, X, Wq, nullptr, nullptr, Q,
                     (q >> 3) * 128, (q & 7) * 128, DD);
    }
}

// Standalone GEMMs
__global__ __launch_bounds__(256, 2) void tc_gemm_f32(
    const half_t* __restrict__ A, const half_t* __restrict__ B,
    float* __restrict__ C, const float* __restrict__ bias)
{
    extern __shared__ char smem[];
    gemm_body<0>(smem, A, B, C, bias, nullptr,
                 blockIdx.y * 128, blockIdx.x * 128, DD);
}

// z-batched KpVp: A += z*BB*KP*DD, B += z*DD*DD, O = z?O1:O0
__global__ __launch_bounds__(256, 2) void tc_gemm_kv(
    const half_t* __restrict__ Xp, const half_t* __restrict__ Wkv,
    half_t* __restrict__ Kp, half_t* __restrict__ Vp)
{
    extern __shared__ char smem[];
    const int z = blockIdx.z;
    gemm_body<1>(smem, Xp + (size_t)z * BB * KP * DD,
                 Wkv + (size_t)z * DD * DD, nullptr, nullptr,
                 z ? Vp : Kp, blockIdx.y * 128, blockIdx.x * 128, DD);
}

// ---------------------------------------------------------------------------
// Fused MMA attention per (bh, 128-row t-tile):
//   S = Q*Kp^T (1-term, fp32 accum), softmax, ctx = P*Vp; ctx plain to Ch.
// Vp load deferred (cp.async group B) to overlap with score MMAs.
// ---------------------------------------------------------------------------
#define AQ 0
#define AK (AQ + 128 * 144)
#define AV (AK + 256 * 144)
#define ATTN_SMEM (AV + 256 * 144)      // 92160

__global__ __launch_bounds__(256) void attn_mma(
    const half_t* __restrict__ Q, const half_t* __restrict__ Kp,
    const half_t* __restrict__ Vp, half_t* __restrict__ Ch)
{
    extern __shared__ char smem[];
    const uint32_t sbase = smem_u32(smem);
    const int tid = threadIdx.x, wid = tid >> 5, lane = tid & 31;
    const int bh = blockIdx.y, b = bh >> 4, h = bh & 15;
    const int t0 = blockIdx.x * 128;

    // Group A: Q + Kp
    const size_t qbase = (size_t)(b * TT + t0) * DD + h * 64;
    for (int idx = tid; idx < 128 * 8; idx += 256) {
        const int r = idx >> 3, c = idx & 7;
        CP_ASYNC16(sbase + AQ + r * 144 + c * 16, Q + qbase + (size_t)r * DD + c * 8);
    }
    const size_t kpb = (size_t)b * KP * DD + h * 64;
    for (int idx = tid; idx < 256 * 8; idx += 256) {
        const int r = idx >> 3, c = idx & 7;
        CP_ASYNC16(sbase + AK + r * 144 + c * 16, Kp + kpb + (size_t)r * DD + c * 8);
    }
    CP_COMMIT();
    // Group B: Vp (consumed only after scores)
    for (int idx = tid; idx < 256 * 8; idx += 256) {
        const int r = idx >> 3, c = idx & 7;
        CP_ASYNC16(sbase + AV + r * 144 + c * 16, Vp + kpb + (size_t)r * DD + c * 8);
    }
    CP_COMMIT();

    CP_WAIT1();          // A done; B may still be in flight
    __syncthreads();

    const int wm = wid * 16;
    const uint32_t lofs = (lane & 15) * 144u + ((lane >> 4) * 16u);

    // --- scores (1-term), ng in batches of 4 ---
    float sacc[32][4];
#pragma unroll
    for (int j = 0; j < 32; j++)
#pragma unroll
        for (int q = 0; q < 4; q++) sacc[j][q] = 0.f;

#pragma unroll
    for (int s = 0; s < 4; s++) {
        uint32_t q4[4], bb[4][4];
        LDMATRIX_X4(q4[0], q4[1], q4[2], q4[3], sbase + AQ + wm * 144 + lofs + s * 32);
#pragma unroll
        for (int g4 = 0; g4 < 4; g4++) {
#pragma unroll
            for (int j = 0; j < 4; j++)
                LDMATRIX_X4(bb[j][0], bb[j][1], bb[j][2], bb[j][3],
                            sbase + AK + (g4 * 4 + j) * (16 * 144) + lofs + s * 32);
#pragma unroll
            for (int j = 0; j < 4; j++) {
                const int ng = g4 * 4 + j;
                MMA_F16(sacc[2 * ng], q4, bb[j][0], bb[j][2]);
                MMA_F16(sacc[2 * ng + 1], q4, bb[j][1], bb[j][3]);
            }
        }
    }

    // --- softmax on fragments ---
    float m0 = -1e30f, m1 = -1e30f;
#pragma unroll
    for (int j = 0; j < 32; j++) {
        m0 = fmaxf(m0, fmaxf(sacc[j][0], sacc[j][1]));
        m1 = fmaxf(m1, fmaxf(sacc[j][2], sacc[j][3]));
    }
    m0 = fmaxf(m0, __shfl_xor_sync(0xffffffffu, m0, 1));
    m0 = fmaxf(m0, __shfl_xor_sync(0xffffffffu, m0, 2));
    m1 = fmaxf(m1, __shfl_xor_sync(0xffffffffu, m1, 1));
    m1 = fmaxf(m1, __shfl_xor_sync(0xffffffffu, m1, 2));

    float sum0 = 0.f, sum1 = 0.f;
#pragma unroll
    for (int j = 0; j < 32; j++) {
        float e0 = __expf((sacc[j][0] - m0) * 0.125f);
        float e1 = __expf((sacc[j][1] - m0) * 0.125f);
        float e2 = __expf((sacc[j][2] - m1) * 0.125f);
        float e3 = __expf((sacc[j][3] - m1) * 0.125f);
        sacc[j][0] = e0; sacc[j][1] = e1; sacc[j][2] = e2; sacc[j][3] = e3;
        sum0 += e0 + e1; sum1 += e2 + e3;
    }
    sum0 += __shfl_xor_sync(0xffffffffu, sum0, 1);
    sum0 += __shfl_xor_sync(0xffffffffu, sum0, 2);
    sum1 += __shfl_xor_sync(0xffffffffu, sum1, 1);
    sum1 += __shfl_xor_sync(0xffffffffu, sum1, 2);
    const float inv0 = __frcp_rn(sum0), inv1 = __frcp_rn(sum1);

    CP_WAIT0();          // Vp landed
    __syncthreads();

    // --- ctx = P * Vp (1-term, P plain fp16) ---
    float cacc[8][4];
#pragma unroll
    for (int nt = 0; nt < 8; nt++)
#pragma unroll
        for (int q = 0; q < 4; q++) cacc[nt][q] = 0.f;

#pragma unroll
    for (int s = 0; s < 16; s++) {
        uint32_t ap[4], bb[4][4];
        ap[0] = pack_h2(sacc[2 * s][0],     sacc[2 * s][1]);
        ap[1] = pack_h2(sacc[2 * s][2],     sacc[2 * s][3]);
        ap[2] = pack_h2(sacc[2 * s + 1][0], sacc[2 * s + 1][1]);
        ap[3] = pack_h2(sacc[2 * s + 1][2], sacc[2 * s + 1][3]);
#pragma unroll
        for (int ng = 0; ng < 4; ng++)
            LDMATRIX_X4_T(bb[ng][0], bb[ng][1], bb[ng][2], bb[ng][3],
                          sbase + AV + s * (16 * 144) + lofs + ng * 32);
#pragma unroll
        for (int ng = 0; ng < 4; ng++) {
            MMA_F16(cacc[2 * ng], ap, bb[ng][0], bb[ng][1]);
            MMA_F16(cacc[2 * ng + 1], ap, bb[ng][2], bb[ng][3]);
        }
    }

    // --- epilogue: normalize, write plain fp16 ctx ---
    const int g = lane >> 2, tig = lane & 3;
    const size_t r0 = (size_t)(b * TT + t0 + wm + g) * DD + h * 64;
    const size_t r1 = r0 + 8 * DD;
#pragma unroll
    for (int nt = 0; nt < 8; nt++) {
        const int col = nt * 8 + 2 * tig;
        *(uint32_t*)(Ch + r0 + col) = pack_h2(cacc[nt][0] * inv0, cacc[nt][1] * inv0);
        *(uint32_t*)(Ch + r1 + col) = pack_h2(cacc[nt][2] * inv1, cacc[nt][3] * inv1);
    }
}

// ---------------------------------------------------------------------------
// Launch
// ---------------------------------------------------------------------------
extern "C" void kernel_launch(void* const* d_in, const int* in_sizes, int n_in,
                              void* d_out, int out_size)
{
    const float* x  = (const float*)d_in[0];
    const float* Wq = (const float*)d_in[1];
    const float* Wk = (const float*)d_in[2];
    const float* Wv = (const float*)d_in[3];
    const float* Ek = (const float*)d_in[4];
    const float* Ev = (const float*)d_in[5];
    const float* Wo = (const float*)d_in[6];
    const float* bo = (const float*)d_in[7];
    float* out = (float*)d_out;

    half_t *Ap, *Qp, *Wtp, *Ethp, *Etlp, *Xpp, *Kpp, *Vpp;
    cudaGetSymbolAddress((void**)&Ap,  g_A);
    cudaGetSymbolAddress((void**)&Qp,  g_Q);
    cudaGetSymbolAddress((void**)&Wtp, g_Wt);
    cudaGetSymbolAddress((void**)&Ethp, g_Eth);
    cudaGetSymbolAddress((void**)&Etlp, g_Etl);
    cudaGetSymbolAddress((void**)&Xpp, g_Xp);
    cudaGetSymbolAddress((void**)&Kpp, g_Kp);
    cudaGetSymbolAddress((void**)&Vpp, g_Vp);

    const size_t WSZ = (size_t)DD * DD;

    cudaFuncSetAttribute(fused_xpq, cudaFuncAttributeMaxDynamicSharedMemorySize, FUSED_SMEM);
    cudaFuncSetAttribute(tc_gemm_f32, cudaFuncAttributeMaxDynamicSharedMemorySize, TC_SMEM);
    cudaFuncSetAttribute(tc_gemm_kv, cudaFuncAttributeMaxDynamicSharedMemorySize, TC_SMEM);
    cudaFuncSetAttribute(attn_mma, cudaFuncAttributeMaxDynamicSharedMemorySize, ATTN_SMEM);

    // 1) convert x -> fp16 plain
    conv_kernel<<<2048, 256>>>(x, Ap, MROWS * DD / 4);
    // 2) transpose+convert weights (plain) + split E
    wconv_kernel<<<dim3(DD / 32, DD / 32, 4), 256>>>(Wq, Wk, Wv, Wo, Wtp);
    esplit_kernel<<<dim3(KP / 32, TT / 32, 2), 256>>>(Ek, Ev, Ethp, Etlp);

    // 3) fused: xp = E^T x (blocks 0..255) + Q = x*Wq (blocks 256..1279)
    fused_xpq<<<1280, 256, FUSED_SMEM>>>(Ethp, Etlp, Ap, Xpp, Wtp, Qp);

    // 4) Kp = xp_k * Wk, Vp = xp_v * Wv (z-batched small GEMMs)
    tc_gemm_kv<<<dim3(DD / 128, (BB * KP) / 128, 2), 256, TC_SMEM>>>(
        Xpp, Wtp + 1 * WSZ, Kpp, Vpp);

    // 5) fused attention -> ctx plain fp16 into A buffer
    attn_mma<<<dim3(TT / 128, BHN), 256, ATTN_SMEM>>>(Qp, Kpp, Vpp, Ap);

    // 6) output projection + bias (fp32 out)
    tc_gemm_f32<<<dim3(DD / 128, MROWS / 128), 256, TC_SMEM>>>(
        Ap, Wtp + 3 * WSZ, out, bo);
}

// round 17
// speedup vs baseline: 2.4520x; 1.0095x over previous
#include <cuda_runtime.h>
#include <cuda_fp16.h>
#include <cstdint>
#include <math.h>

// Problem constants
#define BB 4
#define TT 4096
#define DD 1024
#define HH 16
#define KP 256
#define DK 64
#define MROWS (BB*TT)          // 16384
#define BHN (BB*HH)            // 64

typedef __half half_t;

// ---------------------------------------------------------------------------
// Scratch (static device globals; no allocation allowed)
// ---------------------------------------------------------------------------
__device__ half_t g_A [(size_t)MROWS * DD];      // x plain fp16 (later ctx plain)
__device__ half_t g_Q [(size_t)MROWS * DD];      // plain
__device__ half_t g_Wt[4][(size_t)DD * DD];      // transposed [N][K], plain
__device__ half_t g_Eth[(size_t)2 * KP * TT];    // E^T split hi [z][kp][t]
__device__ half_t g_Etl[(size_t)2 * KP * TT];    // E^T split lo
__device__ half_t g_Xp[(size_t)2 * BB * KP * DD];// xp = E^T x  [z][b][kp][d]
__device__ half_t g_Kp[(size_t)BB * KP * DD];    // Kp [b][kp][d], d = h*64+dk
__device__ half_t g_Vp[(size_t)BB * KP * DD];

// ---------------------------------------------------------------------------
// Helpers
// ---------------------------------------------------------------------------
__device__ __forceinline__ uint32_t smem_u32(const void* p) {
    uint32_t a;
    asm("{ .reg .u64 t; cvta.to.shared.u64 t, %1; cvt.u32.u64 %0, t; }" : "=r"(a) : "l"(p));
    return a;
}

#define CP_ASYNC16(dst, src) \
    asm volatile("cp.async.cg.shared.global [%0], [%1], 16;" :: "r"(dst), "l"(src))
#define CP_COMMIT() asm volatile("cp.async.commit_group;")
#define CP_WAIT1()  asm volatile("cp.async.wait_group 1;" ::: "memory")
#define CP_WAIT0()  asm volatile("cp.async.wait_group 0;" ::: "memory")

#define LDMATRIX_X4(r0, r1, r2, r3, addr) \
    asm volatile("ldmatrix.sync.aligned.m8n8.x4.shared.b16 {%0,%1,%2,%3}, [%4];" \
        : "=r"(r0), "=r"(r1), "=r"(r2), "=r"(r3) : "r"(addr))
#define LDMATRIX_X4_T(r0, r1, r2, r3, addr) \
    asm volatile("ldmatrix.sync.aligned.m8n8.x4.trans.shared.b16 {%0,%1,%2,%3}, [%4];" \
        : "=r"(r0), "=r"(r1), "=r"(r2), "=r"(r3) : "r"(addr))

#define MMA_F16(d, a, b0_, b1_) \
    asm volatile("mma.sync.aligned.m16n8k16.row.col.f32.f16.f16.f32 " \
        "{%0,%1,%2,%3},{%4,%5,%6,%7},{%8,%9},{%0,%1,%2,%3};" \
        : "+f"((d)[0]), "+f"((d)[1]), "+f"((d)[2]), "+f"((d)[3]) \
        : "r"((a)[0]), "r"((a)[1]), "r"((a)[2]), "r"((a)[3]), "r"(b0_), "r"(b1_))

__device__ __forceinline__ uint32_t pack_h2(float a, float b) {
    __half2 t = __floats2half2_rn(a, b);
    return *(uint32_t*)&t;
}

// ---------------------------------------------------------------------------
// Unified preprocessing kernel (block-range dispatch):
//   [0, 4096)     : wconv — transpose+convert 4 weights
//   [4096, 6144)  : esplit — transpose+split Ek/Ev
//   [6144, 8192)  : conv — x fp32 -> fp16 (grid-stride over 2048 virtual blocks)
// ---------------------------------------------------------------------------
__global__ __launch_bounds__(256) void preproc_kernel(
    const float* __restrict__ x,
    const float* __restrict__ W0, const float* __restrict__ W1,
    const float* __restrict__ W2, const float* __restrict__ W3,
    const float* __restrict__ E0, const float* __restrict__ E1,
    half_t* __restrict__ Adst, half_t* __restrict__ WtAll,
    half_t* __restrict__ EhiT, half_t* __restrict__ EloT)
{
    __shared__ float t[32][33];
    const int bid = blockIdx.x;
    const int tx = threadIdx.x & 31, ty = threadIdx.x >> 5;

    if (bid < 4096) {
        // --- wconv: z = bid/1024; 32x32 tile grid over [D][D] ---
        const int z = bid >> 10, rem = bid & 1023;
        const float* W = (z == 0) ? W0 : (z == 1) ? W1 : (z == 2) ? W2 : W3;
        half_t* Wt = WtAll + (size_t)z * DD * DD;
        const int c0 = (rem & 31) * 32, r0 = (rem >> 5) * 32;
#pragma unroll
        for (int r = 0; r < 32; r += 8)
            t[ty + r][tx] = W[(size_t)(r0 + ty + r) * DD + c0 + tx];
        __syncthreads();
#pragma unroll
        for (int r = 0; r < 32; r += 8)
            Wt[(size_t)(c0 + ty + r) * DD + r0 + tx] = __float2half(t[tx][ty + r]);
    } else if (bid < 6144) {
        // --- esplit: i = bid-4096; z = i/1024; 8x128 tile grid over [T][KP] ---
        const int i = bid - 4096;
        const int z = i >> 10, rem = i & 1023;
        const float* E = z ? E1 : E0;
        half_t* hi = EhiT + (size_t)z * KP * TT;
        half_t* lo = EloT + (size_t)z * KP * TT;
        const int c0 = (rem & 7) * 32, r0 = (rem >> 3) * 32;
#pragma unroll
        for (int r = 0; r < 32; r += 8)
            t[ty + r][tx] = E[(size_t)(r0 + ty + r) * KP + c0 + tx];
        __syncthreads();
#pragma unroll
        for (int r = 0; r < 32; r += 8) {
            float v = t[tx][ty + r];
            half_t h = __float2half(v);
            size_t o = (size_t)(c0 + ty + r) * TT + r0 + tx;
            hi[o] = h;
            lo[o] = __float2half(v - __half2float(h));
        }
    } else {
        // --- conv: virtual blocks [0,2048), grid-stride over n4 ---
        const int vb = bid - 6144;
        uint32_t* d2 = (uint32_t*)Adst;
        const int n4 = MROWS * DD / 4;
        const int stride = 2048 * 256;
        for (int i = vb * 256 + threadIdx.x; i < n4; i += stride) {
            float4 v = ((const float4*)x)[i];
            d2[2 * i + 0] = pack_h2(v.x, v.y);
            d2[2 * i + 1] = pack_h2(v.z, v.w);
        }
    }
}

// ---------------------------------------------------------------------------
// GEMM tile constants
// ---------------------------------------------------------------------------
#define GTILE   10240                  // 128 rows * 80 B
#define GSTAGE  (2 * GTILE)            // A, B
#define TC_SMEM (3 * GSTAGE)           // 61440

#define PAH 0
#define PALo 10240
#define PB  20480
#define PSTAGE (PB + 32 * 144)          // 25088
#define PROJ_SMEM (3 * PSTAGE)          // 75264
#define FUSED_SMEM PROJ_SMEM            // max(61440, 75264)

// ---------------------------------------------------------------------------
// GEMM device body (1-term A, plain B). MODE 0: fp32 out (+bias); else fp16.
// ---------------------------------------------------------------------------
template<int MODE>
__device__ __forceinline__ void gemm_body(
    char* smem, const half_t* __restrict__ A, const half_t* __restrict__ B,
    float* __restrict__ C, const float* __restrict__ bias,
    half_t* __restrict__ O, int m0, int n0g, int Kn)
{
    const uint32_t sbase = smem_u32(smem);
    const int tid = threadIdx.x, wid = tid >> 5, lane = tid & 31;
    const int warp_m = wid >> 1, warp_n = wid & 1;

    float acc[2][8][4];
#pragma unroll
    for (int mt = 0; mt < 2; mt++)
#pragma unroll
        for (int nt = 0; nt < 8; nt++)
#pragma unroll
            for (int q = 0; q < 4; q++) acc[mt][nt][q] = 0.f;

    const uint32_t lofs = ((((lane >> 3) & 1) * 8 + (lane & 7)) * 80u) + ((lane >> 4) * 16u);
    const int ld_row0 = tid >> 2;
    const int ld_col  = tid & 3;

    const int NC = Kn >> 5;
#define LOAD_STAGE(s, k0v) do {                                                   \
        const uint32_t stg = sbase + (uint32_t)(s) * GSTAGE;                      \
        _Pragma("unroll")                                                         \
        for (int i = 0; i < 4; i++) {                                             \
            const int t = i >> 1;                                                 \
            const int row = (i & 1) * 64 + ld_row0;                               \
            const half_t* sp = (t == 0 ? A : B);                                  \
            const int grow = (t == 0 ? m0 : n0g) + row;                           \
            CP_ASYNC16(stg + t * GTILE + row * 80 + ld_col * 16,                  \
                       sp + (size_t)grow * Kn + (k0v) + ld_col * 8);              \
        }                                                                         \
        CP_COMMIT();                                                              \
    } while (0)

    LOAD_STAGE(0, 0);
    LOAD_STAGE(1, 32);

    for (int c = 0; c < NC; c++) {
        const bool more = (c + 2 < NC);
        if (more) { CP_WAIT1(); } else { CP_WAIT0(); }   // tail: full drain
        __syncthreads();
        if (more) LOAD_STAGE((c + 2) % 3, (c + 2) << 5);

        const uint32_t stg = sbase + (uint32_t)(c % 3) * GSTAGE;
        const uint32_t a_base = stg + (warp_m * 32) * 80 + lofs;
        const uint32_t b_base = stg + GTILE + (warp_n * 64) * 80 + lofs;

#pragma unroll
        for (int ks = 0; ks < 2; ks++) {
            uint32_t ah[2][4], b[4][4];
#pragma unroll
            for (int mt = 0; mt < 2; mt++)
                LDMATRIX_X4(ah[mt][0], ah[mt][1], ah[mt][2], ah[mt][3],
                            a_base + mt * (16 * 80) + ks * 32);
#pragma unroll
            for (int nq = 0; nq < 4; nq++)
                LDMATRIX_X4(b[nq][0], b[nq][1], b[nq][2], b[nq][3],
                            b_base + nq * (16 * 80) + ks * 32);
#pragma unroll
            for (int mt = 0; mt < 2; mt++)
#pragma unroll
                for (int nt = 0; nt < 8; nt++) {
                    const int nq = nt >> 1, sel = nt & 1;
                    MMA_F16(acc[mt][nt], ah[mt], b[nq][sel], b[nq][sel + 2]);
                }
        }
    }
#undef LOAD_STAGE

    const int g = lane >> 2, tig = lane & 3;
#pragma unroll
    for (int mt = 0; mt < 2; mt++) {
        const int row0 = m0 + warp_m * 32 + mt * 16 + g;
#pragma unroll
        for (int nt = 0; nt < 8; nt++) {
            const int colg = n0g + warp_n * 64 + nt * 8 + 2 * tig;
            if (MODE == 0) {
                float bx = bias[colg], by = bias[colg + 1];
                *(float2*)(C + (size_t)row0 * DD + colg) =
                    make_float2(acc[mt][nt][0] + bx, acc[mt][nt][1] + by);
                *(float2*)(C + (size_t)(row0 + 8) * DD + colg) =
                    make_float2(acc[mt][nt][2] + bx, acc[mt][nt][3] + by);
            } else {
                const size_t o0 = (size_t)row0 * DD + colg;
                const size_t o1 = (size_t)(row0 + 8) * DD + colg;
                *(uint32_t*)(O + o0) = pack_h2(acc[mt][nt][0], acc[mt][nt][1]);
                *(uint32_t*)(O + o1) = pack_h2(acc[mt][nt][2], acc[mt][nt][3]);
            }
        }
    }
}

// ---------------------------------------------------------------------------
// xp device body: xp = E^T x  (2-term E split, fp32 accum)
// ---------------------------------------------------------------------------
__device__ __forceinline__ void xp_body(
    char* smem, const half_t* __restrict__ Eh, const half_t* __restrict__ El,
    const half_t* __restrict__ X, half_t* __restrict__ Xp,
    int m0k, int b, int n64, int z)
{
    const uint32_t sbase = smem_u32(smem);
    const int tid = threadIdx.x, wid = tid >> 5, lane = tid & 31;

    const size_t eoff = (size_t)z * KP * TT;
    const size_t brow = (size_t)b * TT;
    const int hcol = n64 * 64;
    half_t* O = Xp + (size_t)z * BB * KP * DD + (size_t)b * KP * DD;

    float cacc[8][4];
#pragma unroll
    for (int nt = 0; nt < 8; nt++)
#pragma unroll
        for (int q = 0; q < 4; q++) cacc[nt][q] = 0.f;

    const uint32_t lofsA = (lane & 15) * 80u + ((lane >> 4) * 16u);
    const uint32_t lofsB = (lane & 15) * 144u + ((lane >> 4) * 16u);
    const int wm = wid * 16;

#define PROJ_LOAD(s, k0v) do {                                                    \
        const uint32_t stg = sbase + (uint32_t)(s) * PSTAGE;                      \
        _Pragma("unroll")                                                         \
        for (int i = 0; i < 2; i++) {                                             \
            const int idx = tid + i * 256;                                        \
            const int r = idx >> 2, cc = idx & 3;                                 \
            const size_t gof = (size_t)(m0k + r) * TT + (k0v) + cc * 8;           \
            CP_ASYNC16(stg + PAH + r * 80 + cc * 16, Eh + eoff + gof);            \
            CP_ASYNC16(stg + PALo + r * 80 + cc * 16, El + eoff + gof);           \
        }                                                                         \
        {                                                                         \
            const int r = tid >> 3, cc = tid & 7;                                 \
            const size_t gof = (brow + (k0v) + r) * DD + hcol + cc * 8;           \
            CP_ASYNC16(stg + PB + r * 144 + cc * 16, X + gof);                    \
        }                                                                         \
        CP_COMMIT();                                                              \
    } while (0)

    PROJ_LOAD(0, 0);
    PROJ_LOAD(1, 32);
    const int NC = TT >> 5;
    for (int c = 0; c < NC; c++) {
        const bool more = (c + 2 < NC);
        if (more) { CP_WAIT1(); } else { CP_WAIT0(); }   // tail: full drain
        __syncthreads();
        if (more) PROJ_LOAD((c + 2) % 3, (c + 2) << 5);

        const uint32_t stg = sbase + (uint32_t)(c % 3) * PSTAGE;
#pragma unroll
        for (int s = 0; s < 2; s++) {
            uint32_t ah[4], al[4], bb[4][4];
            LDMATRIX_X4(ah[0], ah[1], ah[2], ah[3], stg + PAH + wm * 80 + lofsA + s * 32);
            LDMATRIX_X4(al[0], al[1], al[2], al[3], stg + PALo + wm * 80 + lofsA + s * 32);
#pragma unroll
            for (int ng = 0; ng < 4; ng++)
                LDMATRIX_X4_T(bb[ng][0], bb[ng][1], bb[ng][2], bb[ng][3],
                              stg + PB + s * (16 * 144) + lofsB + ng * 32);
#pragma unroll
            for (int ng = 0; ng < 4; ng++) {
                MMA_F16(cacc[2 * ng], ah, bb[ng][0], bb[ng][1]);
                MMA_F16(cacc[2 * ng + 1], ah, bb[ng][2], bb[ng][3]);
            }
#pragma unroll
            for (int ng = 0; ng < 4; ng++) {
                MMA_F16(cacc[2 * ng], al, bb[ng][0], bb[ng][1]);
                MMA_F16(cacc[2 * ng + 1], al, bb[ng][2], bb[ng][3]);
            }
        }
    }
#undef PROJ_LOAD

    const int g = lane >> 2, tig = lane & 3;
#pragma unroll
    for (int nt = 0; nt < 8; nt++) {
        const int row0 = m0k + wm + g;
        const int col = hcol + nt * 8 + 2 * tig;
        *(uint32_t*)(O + (size_t)row0 * DD + col) =
            pack_h2(cacc[nt][0], cacc[nt][1]);
        *(uint32_t*)(O + (size_t)(row0 + 8) * DD + col) =
            pack_h2(cacc[nt][2], cacc[nt][3]);
    }
}

// ---------------------------------------------------------------------------
// Fused launch: blocks [0,256) run xp (scheduled first), [256,1280) run Q GEMM.
// ---------------------------------------------------------------------------
__global__ __launch_bounds__(256, 2) void fused_xpq(
    const half_t* __restrict__ Eh, const half_t* __restrict__ El,
    const half_t* __restrict__ X, half_t* __restrict__ Xp,
    const half_t* __restrict__ Wq, half_t* __restrict__ Q)
{
    extern __shared__ char smem[];
    const int bid = blockIdx.x;
    if (bid < 256) {
        const int m0k = (bid & 1) * 128;
        const int y = (bid >> 1) & 63;
        const int z = bid >> 7;
        xp_body(smem, Eh, El, X, Xp, m0k, y >> 4, y & 15, z);
    } else {
        const int q = bid - 256;
        gemm_body<1>(smem, X, Wq, nullptr, nullptr, Q,
                     (q >> 3) * 128, (q & 7) * 128, DD);
    }
}

// Standalone GEMMs
__global__ __launch_bounds__(256, 2) void tc_gemm_f32(
    const half_t* __restrict__ A, const half_t* __restrict__ B,
    float* __restrict__ C, const float* __restrict__ bias)
{
    extern __shared__ char smem[];
    gemm_body<0>(smem, A, B, C, bias, nullptr,
                 blockIdx.y * 128, blockIdx.x * 128, DD);
}

// z-batched KpVp: A += z*BB*KP*DD, B += z*DD*DD, O = z?O1:O0
__global__ __launch_bounds__(256, 2) void tc_gemm_kv(
    const half_t* __restrict__ Xp, const half_t* __restrict__ Wkv,
    half_t* __restrict__ Kp, half_t* __restrict__ Vp)
{
    extern __shared__ char smem[];
    const int z = blockIdx.z;
    gemm_body<1>(smem, Xp + (size_t)z * BB * KP * DD,
                 Wkv + (size_t)z * DD * DD, nullptr, nullptr,
                 z ? Vp : Kp, blockIdx.y * 128, blockIdx.x * 128, DD);
}

// ---------------------------------------------------------------------------
// Fused MMA attention per (bh, 128-row t-tile):
//   S = Q*Kp^T (1-term, fp32 accum), softmax, ctx = P*Vp; ctx plain to Ch.
// Vp load deferred (cp.async group B) to overlap with score MMAs.
// ---------------------------------------------------------------------------
#define AQ 0
#define AK (AQ + 128 * 144)
#define AV (AK + 256 * 144)
#define ATTN_SMEM (AV + 256 * 144)      // 92160

__global__ __launch_bounds__(256) void attn_mma(
    const half_t* __restrict__ Q, const half_t* __restrict__ Kp,
    const half_t* __restrict__ Vp, half_t* __restrict__ Ch)
{
    extern __shared__ char smem[];
    const uint32_t sbase = smem_u32(smem);
    const int tid = threadIdx.x, wid = tid >> 5, lane = tid & 31;
    const int bh = blockIdx.y, b = bh >> 4, h = bh & 15;
    const int t0 = blockIdx.x * 128;

    // Group A: Q + Kp
    const size_t qbase = (size_t)(b * TT + t0) * DD + h * 64;
    for (int idx = tid; idx < 128 * 8; idx += 256) {
        const int r = idx >> 3, c = idx & 7;
        CP_ASYNC16(sbase + AQ + r * 144 + c * 16, Q + qbase + (size_t)r * DD + c * 8);
    }
    const size_t kpb = (size_t)b * KP * DD + h * 64;
    for (int idx = tid; idx < 256 * 8; idx += 256) {
        const int r = idx >> 3, c = idx & 7;
        CP_ASYNC16(sbase + AK + r * 144 + c * 16, Kp + kpb + (size_t)r * DD + c * 8);
    }
    CP_COMMIT();
    // Group B: Vp (consumed only after scores)
    for (int idx = tid; idx < 256 * 8; idx += 256) {
        const int r = idx >> 3, c = idx & 7;
        CP_ASYNC16(sbase + AV + r * 144 + c * 16, Vp + kpb + (size_t)r * DD + c * 8);
    }
    CP_COMMIT();

    CP_WAIT1();          // A done; B may still be in flight
    __syncthreads();

    const int wm = wid * 16;
    const uint32_t lofs = (lane & 15) * 144u + ((lane >> 4) * 16u);

    // --- scores (1-term), ng in batches of 4 ---
    float sacc[32][4];
#pragma unroll
    for (int j = 0; j < 32; j++)
#pragma unroll
        for (int q = 0; q < 4; q++) sacc[j][q] = 0.f;

#pragma unroll
    for (int s = 0; s < 4; s++) {
        uint32_t q4[4], bb[4][4];
        LDMATRIX_X4(q4[0], q4[1], q4[2], q4[3], sbase + AQ + wm * 144 + lofs + s * 32);
#pragma unroll
        for (int g4 = 0; g4 < 4; g4++) {
#pragma unroll
            for (int j = 0; j < 4; j++)
                LDMATRIX_X4(bb[j][0], bb[j][1], bb[j][2], bb[j][3],
                            sbase + AK + (g4 * 4 + j) * (16 * 144) + lofs + s * 32);
#pragma unroll
            for (int j = 0; j < 4; j++) {
                const int ng = g4 * 4 + j;
                MMA_F16(sacc[2 * ng], q4, bb[j][0], bb[j][2]);
                MMA_F16(sacc[2 * ng + 1], q4, bb[j][1], bb[j][3]);
            }
        }
    }

    // --- softmax on fragments ---
    float m0 = -1e30f, m1 = -1e30f;
#pragma unroll
    for (int j = 0; j < 32; j++) {
        m0 = fmaxf(m0, fmaxf(sacc[j][0], sacc[j][1]));
        m1 = fmaxf(m1, fmaxf(sacc[j][2], sacc[j][3]));
    }
    m0 = fmaxf(m0, __shfl_xor_sync(0xffffffffu, m0, 1));
    m0 = fmaxf(m0, __shfl_xor_sync(0xffffffffu, m0, 2));
    m1 = fmaxf(m1, __shfl_xor_sync(0xffffffffu, m1, 1));
    m1 = fmaxf(m1, __shfl_xor_sync(0xffffffffu, m1, 2));

    float sum0 = 0.f, sum1 = 0.f;
#pragma unroll
    for (int j = 0; j < 32; j++) {
        float e0 = __expf((sacc[j][0] - m0) * 0.125f);
        float e1 = __expf((sacc[j][1] - m0) * 0.125f);
        float e2 = __expf((sacc[j][2] - m1) * 0.125f);
        float e3 = __expf((sacc[j][3] - m1) * 0.125f);
        sacc[j][0] = e0; sacc[j][1] = e1; sacc[j][2] = e2; sacc[j][3] = e3;
        sum0 += e0 + e1; sum1 += e2 + e3;
    }
    sum0 += __shfl_xor_sync(0xffffffffu, sum0, 1);
    sum0 += __shfl_xor_sync(0xffffffffu, sum0, 2);
    sum1 += __shfl_xor_sync(0xffffffffu, sum1, 1);
    sum1 += __shfl_xor_sync(0xffffffffu, sum1, 2);
    const float inv0 = __frcp_rn(sum0), inv1 = __frcp_rn(sum1);

    CP_WAIT0();          // Vp landed
    __syncthreads();

    // --- ctx = P * Vp (1-term, P plain fp16) ---
    float cacc[8][4];
#pragma unroll
    for (int nt = 0; nt < 8; nt++)
#pragma unroll
        for (int q = 0; q < 4; q++) cacc[nt][q] = 0.f;

#pragma unroll
    for (int s = 0; s < 16; s++) {
        uint32_t ap[4], bb[4][4];
        ap[0] = pack_h2(sacc[2 * s][0],     sacc[2 * s][1]);
        ap[1] = pack_h2(sacc[2 * s][2],     sacc[2 * s][3]);
        ap[2] = pack_h2(sacc[2 * s + 1][0], sacc[2 * s + 1][1]);
        ap[3] = pack_h2(sacc[2 * s + 1][2], sacc[2 * s + 1][3]);
#pragma unroll
        for (int ng = 0; ng < 4; ng++)
            LDMATRIX_X4_T(bb[ng][0], bb[ng][1], bb[ng][2], bb[ng][3],
                          sbase + AV + s * (16 * 144) + lofs + ng * 32);
#pragma unroll
        for (int ng = 0; ng < 4; ng++) {
            MMA_F16(cacc[2 * ng], ap, bb[ng][0], bb[ng][1]);
            MMA_F16(cacc[2 * ng + 1], ap, bb[ng][2], bb[ng][3]);
        }
    }

    // --- epilogue: normalize, write plain fp16 ctx ---
    const int g = lane >> 2, tig = lane & 3;
    const size_t r0 = (size_t)(b * TT + t0 + wm + g) * DD + h * 64;
    const size_t r1 = r0 + 8 * DD;
#pragma unroll
    for (int nt = 0; nt < 8; nt++) {
        const int col = nt * 8 + 2 * tig;
        *(uint32_t*)(Ch + r0 + col) = pack_h2(cacc[nt][0] * inv0, cacc[nt][1] * inv0);
        *(uint32_t*)(Ch + r1 + col) = pack_h2(cacc[nt][2] * inv1, cacc[nt][3] * inv1);
    }
}

// ---------------------------------------------------------------------------
// Launch
// ---------------------------------------------------------------------------
extern "C" void kernel_launch(void* const* d_in, const int* in_sizes, int n_in,
                              void* d_out, int out_size)
{
    const float* x  = (const float*)d_in[0];
    const float* Wq = (const float*)d_in[1];
    const float* Wk = (const float*)d_in[2];
    const float* Wv = (const float*)d_in[3];
    const float* Ek = (const float*)d_in[4];
    const float* Ev = (const float*)d_in[5];
    const float* Wo = (const float*)d_in[6];
    const float* bo = (const float*)d_in[7];
    float* out = (float*)d_out;

    half_t *Ap, *Qp, *Wtp, *Ethp, *Etlp, *Xpp, *Kpp, *Vpp;
    cudaGetSymbolAddress((void**)&Ap,  g_A);
    cudaGetSymbolAddress((void**)&Qp,  g_Q);
    cudaGetSymbolAddress((void**)&Wtp, g_Wt);
    cudaGetSymbolAddress((void**)&Ethp, g_Eth);
    cudaGetSymbolAddress((void**)&Etlp, g_Etl);
    cudaGetSymbolAddress((void**)&Xpp, g_Xp);
    cudaGetSymbolAddress((void**)&Kpp, g_Kp);
    cudaGetSymbolAddress((void**)&Vpp, g_Vp);

    const size_t WSZ = (size_t)DD * DD;

    cudaFuncSetAttribute(fused_xpq, cudaFuncAttributeMaxDynamicSharedMemorySize, FUSED_SMEM);
    cudaFuncSetAttribute(tc_gemm_f32, cudaFuncAttributeMaxDynamicSharedMemorySize, TC_SMEM);
    cudaFuncSetAttribute(tc_gemm_kv, cudaFuncAttributeMaxDynamicSharedMemorySize, TC_SMEM);
    cudaFuncSetAttribute(attn_mma, cudaFuncAttributeMaxDynamicSharedMemorySize, ATTN_SMEM);

    // 1) unified preprocessing: wconv + esplit + conv in one launch
    preproc_kernel<<<8192, 256>>>(x, Wq, Wk, Wv, Wo, Ek, Ev,
                                  Ap, Wtp, Ethp, Etlp);

    // 2) fused: xp = E^T x (blocks 0..255) + Q = x*Wq (blocks 256..1279)
    fused_xpq<<<1280, 256, FUSED_SMEM>>>(Ethp, Etlp, Ap, Xpp, Wtp, Qp);

    // 3) Kp = xp_k * Wk, Vp = xp_v * Wv (z-batched small GEMMs)
    tc_gemm_kv<<<dim3(DD / 128, (BB * KP) / 128, 2), 256, TC_SMEM>>>(
        Xpp, Wtp + 1 * WSZ, Kpp, Vpp);

    // 4) fused attention -> ctx plain fp16 into A buffer
    attn_mma<<<dim3(TT / 128, BHN), 256, ATTN_SMEM>>>(Qp, Kpp, Vpp, Ap);

    // 5) output projection + bias (fp32 out)
    tc_gemm_f32<<<dim3(DD / 128, MROWS / 128), 256, TC_SMEM>>>(
        Ap, Wtp + 3 * WSZ, out, bo);
}